// round 15
// baseline (speedup 1.0000x reference)
#include <cuda_runtime.h>
#include <cuda_bf16.h>
#include <cstdint>
#include <cstddef>

#define B_ 4
#define T_ 8192
#define DIM_ 512
#define DIM2_ 256
#define K4_ 128            // 512 / 4 int8 per u32
#define H_ 8
#define D_ 64
#define C_ 64
#define N_ 128
#define BH_ 32
#define EPSV 1.1920929e-07f
#define MAX_LR 0.01f

// ---------------- scratch (static device globals; no allocations) ----------------
__device__ float g_s  [(size_t)B_*T_*DIM_];     // rmsnorm(seq) fp32 (for proj)
__device__ uint32_t g_aqh[(size_t)B_*T_*K4_];   // rmsnorm(seq) int8 hi (4-packed along k)
__device__ uint32_t g_aql[(size_t)B_*T_*K4_];   // int8 lo
__device__ float g_asc[(size_t)B_*T_];          // per-row scale amax/16256
__device__ float g_kv [(size_t)B_*T_*2*DIM_];   // [k | v]
__device__ float g_q  [(size_t)B_*T_*DIM_];     // s @ Wq
__device__ float g_g1 [(size_t)BH_*N_*D_*D_];   // -grad w1 -> W1eff after scan
__device__ float g_g2 [(size_t)BH_*N_*D_*D_];   // -grad w2 -> W2eff after scan
__device__ uint32_t g_vhp[(size_t)B_*T_*DIM2_]; // merged vals bf16x2 hi
__device__ uint32_t g_vlp[(size_t)B_*T_*DIM2_]; // bf16x2 lo
__device__ float g_lr  [(size_t)B_*T_*H_];
__device__ float g_gate[(size_t)B_*T_*H_];
__device__ float g_mom [(size_t)B_*N_*H_];
__device__ float g_dec [(size_t)B_*N_*H_];
// int8-quantized store weights [N][K4] + per-col scales
__device__ uint32_t g_wkvqh[2*DIM_*K4_], g_wkvql[2*DIM_*K4_];
__device__ float    g_wkvsc[2*DIM_];
__device__ uint32_t g_wqqh [DIM_*K4_],   g_wqql [DIM_*K4_];
__device__ float    g_wqsc [DIM_];
// bf16 out-gemm weight (R12 layout [K2][N])
__device__ uint32_t g_wch [DIM2_*DIM_],  g_wcl [DIM2_*DIM_];

__device__ __forceinline__ float sigmoidf_(float x) { return 1.f / (1.f + expf(-x)); }

__device__ __forceinline__ uint32_t f2tf(float x) {
    uint32_t r;
    asm("cvt.rna.tf32.f32 %0, %1;" : "=r"(r) : "f"(x));
    return r;
}

__device__ __forceinline__ float bf16f(float x) {
    return __bfloat162float(__float2bfloat16(x));
}

__device__ __forceinline__ uint32_t pack_bf2(float e0, float e1) {
    uint32_t r;
    asm("cvt.rn.bf16x2.f32 %0, %1, %2;" : "=r"(r) : "f"(e1), "f"(e0));
    return r;
}

__device__ __forceinline__ void mma_tf32(float c[4], const uint32_t a[4],
                                         uint32_t b0, uint32_t b1) {
    asm volatile(
        "mma.sync.aligned.m16n8k8.row.col.f32.tf32.tf32.f32 "
        "{%0,%1,%2,%3},{%4,%5,%6,%7},{%8,%9},{%0,%1,%2,%3};"
        : "+f"(c[0]), "+f"(c[1]), "+f"(c[2]), "+f"(c[3])
        : "r"(a[0]), "r"(a[1]), "r"(a[2]), "r"(a[3]), "r"(b0), "r"(b1));
}

__device__ __forceinline__ void mma_bf16(float c[4], const uint32_t a[4],
                                         uint32_t b0, uint32_t b1) {
    asm volatile(
        "mma.sync.aligned.m16n8k16.row.col.f32.bf16.bf16.f32 "
        "{%0,%1,%2,%3},{%4,%5,%6,%7},{%8,%9},{%0,%1,%2,%3};"
        : "+f"(c[0]), "+f"(c[1]), "+f"(c[2]), "+f"(c[3])
        : "r"(a[0]), "r"(a[1]), "r"(a[2]), "r"(a[3]), "r"(b0), "r"(b1));
}

__device__ __forceinline__ void mma_s8(int c[4], const uint32_t a[4],
                                       uint32_t b0, uint32_t b1) {
    asm volatile(
        "mma.sync.aligned.m16n8k32.row.col.s32.s8.s8.s32 "
        "{%0,%1,%2,%3},{%4,%5,%6,%7},{%8,%9},{%0,%1,%2,%3};"
        : "+r"(c[0]), "+r"(c[1]), "+r"(c[2]), "+r"(c[3])
        : "r"(a[0]), "r"(a[1]), "r"(a[2]), "r"(a[3]), "r"(b0), "r"(b1));
}

__device__ __forceinline__ void cp16(uint32_t dst, const void* src) {
    asm volatile("cp.async.cg.shared.global [%0], [%1], 16;" :: "r"(dst), "l"(src));
}

// ---------------- K1: rmsnorm, emits fp32 + int8 hi/lo (15-bit) + row scale ----------------
__global__ __launch_bounds__(256) void rmsnorm_kernel(const float* __restrict__ seq) {
    size_t row = blockIdx.x;
    const float2* in2 = (const float2*)(seq + row * DIM_);
    int tid = threadIdx.x;
    float2 v = in2[tid];
    float ss = v.x * v.x + v.y * v.y;
    float am = fmaxf(fabsf(v.x), fabsf(v.y));
#pragma unroll
    for (int o = 16; o; o >>= 1) {
        ss += __shfl_xor_sync(0xffffffffu, ss, o);
        am = fmaxf(am, __shfl_xor_sync(0xffffffffu, am, o));
    }
    __shared__ float wsum[8], wmax[8];
    if ((tid & 31) == 0) { wsum[tid >> 5] = ss; wmax[tid >> 5] = am; }
    __syncthreads();
    float tot = 0.f, amax = 0.f;
#pragma unroll
    for (int w = 0; w < 8; w++) { tot += wsum[w]; amax = fmaxf(amax, wmax[w]); }
    float sc = rsqrtf(tot * (1.f / DIM_) + EPSV);
    float o0 = v.x * sc, o1 = v.y * sc;
    ((float2*)(g_s + row * DIM_))[tid] = make_float2(o0, o1);
    float amo = fmaxf(amax * sc, 1e-30f);
    float Sa = 16256.f / amo;
    int q0 = lrintf(o0 * Sa), q1 = lrintf(o1 * Sa);
    int h0 = (q0 + 64) >> 7, h1 = (q1 + 64) >> 7;
    int l0 = q0 - (h0 << 7), l1 = q1 - (h1 << 7);
    ((uint16_t*)g_aqh)[row * 256 + tid] = (uint16_t)((h0 & 255) | ((h1 & 255) << 8));
    ((uint16_t*)g_aql)[row * 256 + tid] = (uint16_t)((l0 & 255) | ((l1 & 255) << 8));
    if (tid == 0) g_asc[row] = amo * (1.f / 16256.f);
}

// ---------------- weight quant: per-column 15-bit int8 split, [N][K4] k-packed ----------------
__global__ __launch_bounds__(128) void wquant_s8(const float* __restrict__ W,
                                                 uint32_t* __restrict__ qh,
                                                 uint32_t* __restrict__ ql,
                                                 float* __restrict__ sc, int Ncols) {
    int n = blockIdx.x;
    int tid = threadIdx.x;   // 128 threads, 4 k each
    float v[4];
#pragma unroll
    for (int i = 0; i < 4; i++) v[i] = W[(size_t)(tid * 4 + i) * Ncols + n];
    float am = fmaxf(fmaxf(fabsf(v[0]), fabsf(v[1])), fmaxf(fabsf(v[2]), fabsf(v[3])));
#pragma unroll
    for (int o = 16; o; o >>= 1) am = fmaxf(am, __shfl_xor_sync(0xffffffffu, am, o));
    __shared__ float wm[4];
    if ((tid & 31) == 0) wm[tid >> 5] = am;
    __syncthreads();
    am = fmaxf(fmaxf(wm[0], wm[1]), fmaxf(wm[2], wm[3]));
    am = fmaxf(am, 1e-30f);
    float S = 16256.f / am;
    uint32_t ph = 0, pl = 0;
#pragma unroll
    for (int i = 0; i < 4; i++) {
        int q = lrintf(v[i] * S);
        int h = (q + 64) >> 7;
        int l = q - (h << 7);
        ph |= (uint32_t)(h & 255) << (i * 8);
        pl |= (uint32_t)(l & 255) << (i * 8);
    }
    qh[(size_t)n * K4_ + tid] = ph;
    ql[(size_t)n * K4_ + tid] = pl;
    if (tid == 0) sc[n] = am * (1.f / 16256.f);
}

// ---------------- bf16 out-gemm weight preconvert: [K2][N] ----------------
__global__ void cvtpack_kernel(const float* __restrict__ src, uint32_t* __restrict__ dh,
                               uint32_t* __restrict__ dl, int K2, int Nc) {
    int i = blockIdx.x * 256 + threadIdx.x;
    if (i < K2 * Nc) {
        int k2 = i / Nc, n = i - k2 * Nc;
        float e0 = src[(size_t)(2 * k2) * Nc + n];
        float e1 = src[(size_t)(2 * k2 + 1) * Nc + n];
        dh[i] = pack_bf2(e0, e1);
        dl[i] = pack_bf2(e0 - bf16f(e0), e1 - bf16f(e1));
    }
}

// ---------------- K2: per-token lr/gate projections + per-chunk mom/decay ----------------
__global__ __launch_bounds__(256) void proj_kernel(const float* __restrict__ Wstep,
                                                   const float* __restrict__ Wgate,
                                                   const float* __restrict__ Wmom,
                                                   const float* __restrict__ Wdecay) {
    int blk = blockIdx.x;              // b*N_ + nn
    int b = blk >> 7, nn = blk & 127;
    size_t tb = (size_t)b * T_ + (size_t)nn * C_;
    int tid = threadIdx.x, lane = tid & 31, w = tid >> 5;

    for (int tk = w; tk < C_; tk += 8) {
        const float* srow = g_s + (tb + tk) * DIM_;
        float acc[16];
#pragma unroll
        for (int q = 0; q < 16; q++) acc[q] = 0.f;
        for (int p = lane; p < DIM_; p += 32) {
            float sv = srow[p];
            const float* ws = Wstep + p * H_;
            const float* wg = Wgate + p * H_;
#pragma unroll
            for (int hh = 0; hh < 8; hh++) {
                acc[hh]     += sv * ws[hh];
                acc[8 + hh] += sv * wg[hh];
            }
        }
#pragma unroll
        for (int q = 0; q < 16; q++)
#pragma unroll
            for (int o = 16; o; o >>= 1) acc[q] += __shfl_xor_sync(0xffffffffu, acc[q], o);
        if (lane == 0) {
#pragma unroll
            for (int hh = 0; hh < 8; hh++) {
                g_lr  [(tb + tk) * H_ + hh] = sigmoidf_(acc[hh]) * MAX_LR;
                g_gate[(tb + tk) * H_ + hh] = sigmoidf_(acc[8 + hh]);
            }
        }
    }

    __shared__ float ssum[DIM_];
    for (int p = tid; p < DIM_; p += 256) {
        float a = 0.f;
        for (int tk = 0; tk < C_; tk++) a += g_s[(tb + tk) * DIM_ + p];
        ssum[p] = a * (1.f / C_);
    }
    __syncthreads();
    if (w < 8) {
        float am = 0.f, ad = 0.f;
        for (int p = lane; p < DIM_; p += 32) {
            am += ssum[p] * Wmom[p * H_ + w];
            ad += ssum[p] * Wdecay[p * H_ + w];
        }
#pragma unroll
        for (int o = 16; o; o >>= 1) {
            am += __shfl_xor_sync(0xffffffffu, am, o);
            ad += __shfl_xor_sync(0xffffffffu, ad, o);
        }
        if (lane == 0) {
            g_mom[((size_t)b * N_ + nn) * H_ + w] = sigmoidf_(am);
            g_dec[((size_t)b * N_ + nn) * H_ + w] = sigmoidf_(ad);
        }
    }
}

// ---------------- gemm_s8: int8 3-term split, 128x128 tile, 512 threads ----------------
// A [M][K4] u32 (4 int8 along k), B [N][K4] u32, C fp32 [M][N].
#define SQ_LD 20
#define SQ_SZ (128 * SQ_LD)
#define SQ_STAGE (4 * SQ_SZ)
#define SQ_SMEM (2 * SQ_STAGE * 4)

__device__ __forceinline__ void s8_issue(uint32_t sb, const uint32_t* __restrict__ Ah,
                                         const uint32_t* __restrict__ Al,
                                         const uint32_t* __restrict__ Bh,
                                         const uint32_t* __restrict__ Bl,
                                         int brow, int bcol, int kt4, int tid) {
    int row = tid >> 2, c4 = (tid & 3) << 2;
    size_t ga = (size_t)(brow + row) * K4_ + kt4 + c4;
    cp16(sb + (row * SQ_LD + c4) * 4, Ah + ga);
    cp16(sb + (SQ_SZ + row * SQ_LD + c4) * 4, Al + ga);
    size_t gb = (size_t)(bcol + row) * K4_ + kt4 + c4;
    cp16(sb + (2 * SQ_SZ + row * SQ_LD + c4) * 4, Bh + gb);
    cp16(sb + (3 * SQ_SZ + row * SQ_LD + c4) * 4, Bl + gb);
}

__global__ __launch_bounds__(512) void gemm_s8(const uint32_t* __restrict__ Ah,
                                               const uint32_t* __restrict__ Al,
                                               const uint32_t* __restrict__ Bh,
                                               const uint32_t* __restrict__ Bl,
                                               const float* __restrict__ asc,
                                               const float* __restrict__ bsc,
                                               float* __restrict__ C, int Nc) {
    extern __shared__ uint32_t smq[];
    int tid = threadIdx.x;
    int lane = tid & 31, warp = tid >> 5;      // 16 warps
    int brow = blockIdx.y * 128, bcol = blockIdx.x * 128;
    int wm = (warp >> 1) * 16, wn = (warp & 1) * 64;
    int g = lane >> 2, tg = lane & 3;
    uint32_t sbase = (uint32_t)__cvta_generic_to_shared(smq);

    float fac[8][4];
#pragma unroll
    for (int ni = 0; ni < 8; ni++)
#pragma unroll
        for (int e = 0; e < 4; e++) fac[ni][e] = 0.f;

    s8_issue(sbase, Ah, Al, Bh, Bl, brow, bcol, 0, tid);
    asm volatile("cp.async.commit_group;");

    const int KT = K4_ >> 4;   // 8 tiles of K=64
    for (int t = 0; t < KT; t++) {
        if (t + 1 < KT) {
            s8_issue(sbase + ((t + 1) & 1) * SQ_STAGE * 4, Ah, Al, Bh, Bl,
                     brow, bcol, (t + 1) << 4, tid);
            asm volatile("cp.async.commit_group;");
            asm volatile("cp.async.wait_group 1;");
        } else {
            asm volatile("cp.async.wait_group 0;");
        }
        __syncthreads();
        const uint32_t* st = smq + (t & 1) * SQ_STAGE;
        const uint32_t* sAh = st;
        const uint32_t* sAl = st + SQ_SZ;
        const uint32_t* sBh = st + 2 * SQ_SZ;
        const uint32_t* sBl = st + 3 * SQ_SZ;

        int hh[8][4], mid[8][4];
#pragma unroll
        for (int ni = 0; ni < 8; ni++)
#pragma unroll
            for (int e = 0; e < 4; e++) { hh[ni][e] = 0; mid[ni][e] = 0; }

#pragma unroll
        for (int kh = 0; kh < 2; kh++) {
            int k4 = kh * 8;
            uint32_t ah[4], al[4];
            int ra = (wm + g) * SQ_LD + k4 + tg;
            int rb8 = ra + 8 * SQ_LD;
            ah[0] = sAh[ra]; ah[1] = sAh[rb8]; ah[2] = sAh[ra + 4]; ah[3] = sAh[rb8 + 4];
            al[0] = sAl[ra]; al[1] = sAl[rb8]; al[2] = sAl[ra + 4]; al[3] = sAl[rb8 + 4];
#pragma unroll
            for (int ni = 0; ni < 8; ni++) {
                int rb = (wn + ni * 8 + g) * SQ_LD + k4 + tg;
                uint32_t bh0 = sBh[rb], bh1 = sBh[rb + 4];
                uint32_t bl0 = sBl[rb], bl1 = sBl[rb + 4];
                mma_s8(hh[ni], ah, bh0, bh1);
                mma_s8(mid[ni], ah, bl0, bl1);
                mma_s8(mid[ni], al, bh0, bh1);
            }
        }
#pragma unroll
        for (int ni = 0; ni < 8; ni++)
#pragma unroll
            for (int e = 0; e < 4; e++)
                fac[ni][e] += (float)hh[ni][e] * 16384.f + (float)mid[ni][e] * 128.f;
        __syncthreads();
    }

    int r0 = brow + wm + g, r1 = r0 + 8;
    float sa0 = asc[r0], sa1 = asc[r1];
#pragma unroll
    for (int ni = 0; ni < 8; ni++) {
        int cx = bcol + wn + ni * 8 + 2 * tg;
        float sb0 = bsc[cx], sb1 = bsc[cx + 1];
        float2 lo = {fac[ni][0] * sa0 * sb0, fac[ni][1] * sa0 * sb1};
        float2 hi = {fac[ni][2] * sa1 * sb0, fac[ni][3] * sa1 * sb1};
        *(float2*)(C + (size_t)r0 * Nc + cx) = lo;
        *(float2*)(C + (size_t)r1 * Nc + cx) = hi;
    }
}

// ---------------- gemm_bf16 (R12): out-gemm only ----------------
#define GA_LD 20
#define GB_LD 136
#define GA_SZ (128 * GA_LD)
#define GB_SZ (16 * GB_LD)
#define GSTAGE (2 * GA_SZ + 2 * GB_SZ)
#define GEMM_SMEM (2 * GSTAGE * 4)

__device__ __forceinline__ void gemm_issue(uint32_t sbase, const uint32_t* __restrict__ Ah,
                                           const uint32_t* __restrict__ Al,
                                           const uint32_t* __restrict__ Bh,
                                           const uint32_t* __restrict__ Bl,
                                           int brow, int bcol, int kt2, int K2, int Nc, int tid) {
    int ra = tid >> 2, ca = (tid & 3) << 2;
    int rb = tid >> 5, cb = (tid & 31) << 2;
#pragma unroll
    for (int p = 0; p < 2; p++) {
        int r = p * 64 + ra;
        size_t ga = (size_t)(brow + r) * K2 + kt2 + ca;
        uint32_t da = sbase + (r * GA_LD + ca) * 4;
        cp16(da, Ah + ga);
        cp16(da + GA_SZ * 4, Al + ga);
        int r2 = p * 8 + rb;
        size_t gb = (size_t)(kt2 + r2) * Nc + bcol + cb;
        uint32_t db = sbase + (2 * GA_SZ + r2 * GB_LD + cb) * 4;
        cp16(db, Bh + gb);
        cp16(db + GB_SZ * 4, Bl + gb);
    }
}

__global__ __launch_bounds__(256, 2) void gemm_bf16(const uint32_t* __restrict__ Ah,
                                                    const uint32_t* __restrict__ Al,
                                                    const uint32_t* __restrict__ Bh,
                                                    const uint32_t* __restrict__ Bl,
                                                    float* __restrict__ C,
                                                    int M, int Nc, int K2) {
    extern __shared__ uint32_t smem_u[];
    int tid = threadIdx.x;
    int lane = tid & 31, warp = tid >> 5;
    int brow = blockIdx.y * 128, bcol = blockIdx.x * 128;
    int wm = (warp >> 1) * 32, wn = (warp & 1) * 64;
    int g = lane >> 2, tg = lane & 3;
    uint32_t sbase = (uint32_t)__cvta_generic_to_shared(smem_u);

    float acc[2][8][4];
#pragma unroll
    for (int mi = 0; mi < 2; mi++)
#pragma unroll
        for (int ni = 0; ni < 8; ni++)
#pragma unroll
            for (int e = 0; e < 4; e++) acc[mi][ni][e] = 0.f;

    gemm_issue(sbase, Ah, Al, Bh, Bl, brow, bcol, 0, K2, Nc, tid);
    asm volatile("cp.async.commit_group;");

    int KT = K2 >> 4;
    for (int t = 0; t < KT; t++) {
        if (t + 1 < KT) {
            gemm_issue(sbase + ((t + 1) & 1) * GSTAGE * 4, Ah, Al, Bh, Bl,
                       brow, bcol, (t + 1) << 4, K2, Nc, tid);
            asm volatile("cp.async.commit_group;");
            asm volatile("cp.async.wait_group 1;");
        } else {
            asm volatile("cp.async.wait_group 0;");
        }
        __syncthreads();
        const uint32_t* st = smem_u + (t & 1) * GSTAGE;
        const uint32_t* sAh = st;
        const uint32_t* sAl = st + GA_SZ;
        const uint32_t* sBh = st + 2 * GA_SZ;
        const uint32_t* sBl = st + 2 * GA_SZ + GB_SZ;
#pragma unroll
        for (int kh = 0; kh < 2; kh++) {
            int k8 = kh * 8;
            uint32_t ah[2][4], al[2][4];
#pragma unroll
            for (int mi = 0; mi < 2; mi++) {
                int r0 = (wm + mi * 16 + g) * GA_LD + k8 + tg;
                int r1 = r0 + 8 * GA_LD;
                ah[mi][0] = sAh[r0];     ah[mi][1] = sAh[r1];
                ah[mi][2] = sAh[r0 + 4]; ah[mi][3] = sAh[r1 + 4];
                al[mi][0] = sAl[r0];     al[mi][1] = sAl[r1];
                al[mi][2] = sAl[r0 + 4]; al[mi][3] = sAl[r1 + 4];
            }
#pragma unroll
            for (int ni = 0; ni < 8; ni++) {
                int nb = (k8 + tg) * GB_LD + wn + ni * 8 + g;
                uint32_t bh0 = sBh[nb], bh1 = sBh[nb + 4 * GB_LD];
                uint32_t bl0 = sBl[nb], bl1 = sBl[nb + 4 * GB_LD];
#pragma unroll
                for (int mi = 0; mi < 2; mi++) {
                    mma_bf16(acc[mi][ni], ah[mi], bh0, bh1);
                    mma_bf16(acc[mi][ni], ah[mi], bl0, bl1);
                    mma_bf16(acc[mi][ni], al[mi], bh0, bh1);
                }
            }
        }
        __syncthreads();
    }

#pragma unroll
    for (int mi = 0; mi < 2; mi++)
#pragma unroll
        for (int ni = 0; ni < 8; ni++) {
            int r = brow + wm + mi * 16 + g;
            int cx = bcol + wn + ni * 8 + tg * 2;
            float2 lo = {acc[mi][ni][0], acc[mi][ni][1]};
            float2 hi = {acc[mi][ni][2], acc[mi][ni][3]};
            *(float2*)(C + (size_t)r * Nc + cx) = lo;
            *(float2*)(C + (size_t)(r + 8) * Nc + cx) = hi;
        }
}

// ---------------- tensor-core 64x64x64 from smem tf32 hi/lo, selectable terms ----------------
#define CLD 68
#define BUF (64 * CLD)

template <bool TA, bool TB, bool AL, bool BL>
__device__ __forceinline__ void mm64_tc(const uint32_t* __restrict__ Ah,
                                        const uint32_t* __restrict__ Al,
                                        const uint32_t* __restrict__ Bh,
                                        const uint32_t* __restrict__ Bl,
                                        float acc[4][4], int m0, int n0, int g, int tg) {
#pragma unroll
    for (int ni = 0; ni < 4; ni++)
#pragma unroll
        for (int e = 0; e < 4; e++) acc[ni][e] = 0.f;
#pragma unroll 2
    for (int k8 = 0; k8 < 64; k8 += 8) {
        uint32_t ah[4], al[4] = {0, 0, 0, 0};
        if (!TA) {
            int ba = (m0 + g) * CLD + k8 + tg;
            ah[0] = Ah[ba]; ah[1] = Ah[ba + 8 * CLD]; ah[2] = Ah[ba + 4]; ah[3] = Ah[ba + 8 * CLD + 4];
            if (AL) {
                al[0] = Al[ba]; al[1] = Al[ba + 8 * CLD]; al[2] = Al[ba + 4]; al[3] = Al[ba + 8 * CLD + 4];
            }
        } else {
            int ba = (k8 + tg) * CLD + m0 + g;
            ah[0] = Ah[ba]; ah[1] = Ah[ba + 8]; ah[2] = Ah[ba + 4 * CLD]; ah[3] = Ah[ba + 4 * CLD + 8];
            if (AL) {
                al[0] = Al[ba]; al[1] = Al[ba + 8]; al[2] = Al[ba + 4 * CLD]; al[3] = Al[ba + 4 * CLD + 8];
            }
        }
#pragma unroll
        for (int ni = 0; ni < 4; ni++) {
            uint32_t bh0, bh1, bl0 = 0, bl1 = 0;
            if (!TB) {
                int bb = (k8 + tg) * CLD + n0 + ni * 8 + g;
                bh0 = Bh[bb]; bh1 = Bh[bb + 4 * CLD];
                if (BL) { bl0 = Bl[bb]; bl1 = Bl[bb + 4 * CLD]; }
            } else {
                int bb = (n0 + ni * 8 + g) * CLD + k8 + tg;
                bh0 = Bh[bb]; bh1 = Bh[bb + 4];
                if (BL) { bl0 = Bl[bb]; bl1 = Bl[bb + 4]; }
            }
            mma_tf32(acc[ni], ah, bh0, bh1);
            if (BL) mma_tf32(acc[ni], ah, bl0, bl1);
            if (AL) mma_tf32(acc[ni], al, bh0, bh1);
        }
    }
}

// fragment (row, col): e0=(g,2tg) e1=(g,2tg+1) e2=(g+8,2tg) e3=(g+8,2tg+1)
#define FRAG_ROW(e) (m0 + g + ((e) >> 1 ? 8 : 0))
#define FRAG_COL(ni, e) (n0 + (ni) * 8 + 2 * tg + ((e) & 1))

// ---------------- K4: per-chunk MLP gradients (6 smem bufs -> 2 CTAs/SM) ----------------
#define CG_SMEM (6 * BUF * 4)
__global__ __launch_bounds__(256, 2) void chunk_grad_tc(const float* __restrict__ w1,
                                                        const float* __restrict__ w2) {
    int id = blockIdx.x;               // bh*N_ + nn
    int bh = id >> 7, nn = id & 127;
    int b = bh >> 3, h = bh & 7;
    size_t tb = (size_t)b * T_ + (size_t)nn * C_;
    extern __shared__ uint32_t smu2[];
    uint32_t* KCh = smu2;
    uint32_t* HHh = smu2 + BUF;
    uint32_t* HHl = smu2 + 2 * BUF;
    uint32_t* W2h = smu2 + 3 * BUF;
    uint32_t* W2l = smu2 + 4 * BUF;
    uint32_t* G2h = smu2 + 5 * BUF;
    __shared__ float lrs[64];
    int tid = threadIdx.x;
    if (tid < 64) lrs[tid] = g_lr[(tb + tid) * H_ + h];
    for (int idx = tid; idx < 4096; idx += 256) {
        int i = idx >> 6, j = idx & 63;
        float kc = g_kv[(tb + i) * (2 * DIM_) + h * 64 + j];
        KCh[i * CLD + j] = f2tf(kc);
        float a1 = w1[idx];
        uint32_t hi = f2tf(a1);
        HHh[i * CLD + j] = hi; HHl[i * CLD + j] = f2tf(a1 - __uint_as_float(hi));
        float a2 = w2[idx];
        hi = f2tf(a2);
        W2h[i * CLD + j] = hi; W2l[i * CLD + j] = f2tf(a2 - __uint_as_float(hi));
    }
    __syncthreads();
    int lane = tid & 31, warp = tid >> 5;
    int m0 = (warp >> 1) * 16, n0 = (warp & 1) * 32;
    int g = lane >> 2, tg = lane & 3;
    float acc[4][4], x1s[4][4];

    // MM1: X1 = KC(hi) @ W1(hi/lo); X1 in regs; HH = silu(X1) hi/lo
    mm64_tc<false, false, false, true>(KCh, nullptr, HHh, HHl, acc, m0, n0, g, tg);
    __syncthreads();
#pragma unroll
    for (int ni = 0; ni < 4; ni++)
#pragma unroll
        for (int e = 0; e < 4; e++) {
            int row = FRAG_ROW(e), col = FRAG_COL(ni, e);
            float x = acc[ni][e];
            x1s[ni][e] = x;
            float hv = x * sigmoidf_(x);
            uint32_t hi = f2tf(hv);
            HHh[row * CLD + col] = hi;
            HHl[row * CLD + col] = f2tf(hv - __uint_as_float(hi));
        }
    __syncthreads();

    // MM2: X2 = HH @ W2 [3-term] ; G2 hi only
    mm64_tc<false, false, true, true>(HHh, HHl, W2h, W2l, acc, m0, n0, g, tg);
#pragma unroll
    for (int ni = 0; ni < 4; ni++)
#pragma unroll
        for (int e = 0; e < 4; e++) {
            int row = FRAG_ROW(e), col = FRAG_COL(ni, e);
            float vc = g_kv[(tb + row) * (2 * DIM_) + DIM_ + h * 64 + col];
            float gg = (2.f / 64.f) * lrs[row] * (acc[ni][e] - vc);
            G2h[row * CLD + col] = f2tf(gg);
        }
    __syncthreads();

    // MM3: g2 = HH^T @ G2(hi) -> -g2
    mm64_tc<true, false, true, false>(HHh, HHl, G2h, nullptr, acc, m0, n0, g, tg);
    size_t gbase = (size_t)id * 4096;
#pragma unroll
    for (int ni = 0; ni < 4; ni++) {
        int col = n0 + ni * 8 + 2 * tg;
        float2 v0 = {-acc[ni][0], -acc[ni][1]};
        float2 v1 = {-acc[ni][2], -acc[ni][3]};
        *(float2*)(g_g2 + gbase + (m0 + g) * 64 + col) = v0;
        *(float2*)(g_g2 + gbase + (m0 + 8 + g) * 64 + col) = v1;
    }
    __syncthreads();

    // MM4: DX1 = (G2(hi) @ W2^T) * silu'(X1) -> HH bufs
    mm64_tc<false, true, false, true>(G2h, nullptr, W2h, W2l, acc, m0, n0, g, tg);
#pragma unroll
    for (int ni = 0; ni < 4; ni++)
#pragma unroll
        for (int e = 0; e < 4; e++) {
            int row = FRAG_ROW(e), col = FRAG_COL(ni, e);
            float x = x1s[ni][e];
            float sg = sigmoidf_(x);
            float dv = acc[ni][e] * sg * (1.f + x * (1.f - sg));
            uint32_t hi = f2tf(dv);
            HHh[row * CLD + col] = hi;
            HHl[row * CLD + col] = f2tf(dv - __uint_as_float(hi));
        }
    __syncthreads();

    // MM5: g1 = KC^T(hi) @ DX1 -> -g1
    mm64_tc<true, false, false, true>(KCh, nullptr, HHh, HHl, acc, m0, n0, g, tg);
#pragma unroll
    for (int ni = 0; ni < 4; ni++) {
        int col = n0 + ni * 8 + 2 * tg;
        float2 v0 = {-acc[ni][0], -acc[ni][1]};
        float2 v1 = {-acc[ni][2], -acc[ni][3]};
        *(float2*)(g_g1 + gbase + (m0 + g) * 64 + col) = v0;
        *(float2*)(g_g1 + gbase + (m0 + 8 + g) * 64 + col) = v1;
    }
}

// ---------------- K5: double assoc-scan over n=128 chunks ----------------
__global__ __launch_bounds__(256) void scan_kernel(const float* __restrict__ w1,
                                                   const float* __restrict__ w2) {
    int bh = blockIdx.y;
    int idx = blockIdx.x * 256 + threadIdx.x;
    int b = bh >> 3, h = bh & 7;
    float w1v = w1[idx], w2v = w2[idx];
    float m1 = 0.f, u1 = 0.f, m2 = 0.f, u2 = 0.f;
    size_t base = ((size_t)bh * N_) * 4096 + idx;
    for (int nn = 0; nn < N_; nn++) {
        float mg = g_mom[((size_t)b * N_ + nn) * H_ + h];
        float dc = g_dec[((size_t)b * N_ + nn) * H_ + h];
        size_t off = base + (size_t)nn * 4096;
        float s1 = g_g1[off], s2 = g_g2[off];
        m1 = mg * m1 + s1; u1 = (1.f - dc) * u1 + m1; g_g1[off] = w1v + u1;
        m2 = mg * m2 + s2; u2 = (1.f - dc) * u2 + m2; g_g2[off] = w2v + u2;
    }
}

// ---------------- zero first 63 rows of packed vals per batch ----------------
__global__ void zero_pad_kernel() {
    int idx = blockIdx.x * 256 + threadIdx.x;
    const int per = 63 * DIM2_;
    if (idx < B_ * per) {
        int b = idx / per, r = idx % per;
        g_vhp[(size_t)b * T_ * DIM2_ + r] = 0u;
        g_vlp[(size_t)b * T_ * DIM2_ + r] = 0u;
    }
}

// ---------------- K6: retrieve (tensor cores, 3x tf32; emits packed bf16 vals) ----------------
#define RT_SMEM (6 * BUF * 4)
__global__ __launch_bounds__(256, 2) void retrieve_tc(const float* __restrict__ gamma) {
    int id = blockIdx.x;
    int bh = id >> 7, nn = id & 127;
    int b = bh >> 3, h = bh & 7;
    extern __shared__ uint32_t smu3[];
    uint32_t* Qh  = smu3;
    uint32_t* Ql  = smu3 + BUF;
    uint32_t* HHh = smu3 + 2 * BUF;   // W1eff first, then HH
    uint32_t* HHl = smu3 + 3 * BUF;
    uint32_t* W2h = smu3 + 4 * BUF;
    uint32_t* W2l = smu3 + 5 * BUF;
    __shared__ float rowp[64][2];
    __shared__ float gam[64];
    __shared__ float rscale[64];
    int tid = threadIdx.x;
    int j0 = nn * C_;
    size_t gbase = (size_t)id * 4096;
    if (tid < 64) gam[tid] = gamma[h * 64 + tid] + 1.f;
    for (int idx = tid; idx < 4096; idx += 256) {
        int ci = idx >> 6, a = idx & 63;
        int i = j0 + ci + 63;
        float qv = (i < T_) ? g_q[((size_t)b * T_ + i) * DIM_ + h * 64 + a] : 0.f;
        uint32_t hi = f2tf(qv);
        Qh[ci * CLD + a] = hi; Ql[ci * CLD + a] = f2tf(qv - __uint_as_float(hi));
        float e1 = g_g1[gbase + idx];
        hi = f2tf(e1);
        HHh[ci * CLD + a] = hi; HHl[ci * CLD + a] = f2tf(e1 - __uint_as_float(hi));
        float e2 = g_g2[gbase + idx];
        hi = f2tf(e2);
        W2h[ci * CLD + a] = hi; W2l[ci * CLD + a] = f2tf(e2 - __uint_as_float(hi));
    }
    __syncthreads();
    int lane = tid & 31, warp = tid >> 5;
    int m0 = (warp >> 1) * 16, n0 = (warp & 1) * 32;
    int g = lane >> 2, tg = lane & 3;
    float acc[4][4];

    mm64_tc<false, false, true, true>(Qh, Ql, HHh, HHl, acc, m0, n0, g, tg);
    __syncthreads();
#pragma unroll
    for (int ni = 0; ni < 4; ni++)
#pragma unroll
        for (int e = 0; e < 4; e++) {
            int row = FRAG_ROW(e), col = FRAG_COL(ni, e);
            float x = acc[ni][e];
            float hv = x * sigmoidf_(x);
            uint32_t hi = f2tf(hv);
            HHh[row * CLD + col] = hi;
            HHl[row * CLD + col] = f2tf(hv - __uint_as_float(hi));
        }
    __syncthreads();

    mm64_tc<false, false, true, true>(HHh, HHl, W2h, W2l, acc, m0, n0, g, tg);

    float ss0 = 0.f, ss1 = 0.f;
#pragma unroll
    for (int ni = 0; ni < 4; ni++) {
        ss0 += acc[ni][0] * acc[ni][0] + acc[ni][1] * acc[ni][1];
        ss1 += acc[ni][2] * acc[ni][2] + acc[ni][3] * acc[ni][3];
    }
#pragma unroll
    for (int o = 1; o < 4; o <<= 1) {
        ss0 += __shfl_xor_sync(0xffffffffu, ss0, o);
        ss1 += __shfl_xor_sync(0xffffffffu, ss1, o);
    }
    if (tg == 0) {
        rowp[m0 + g][warp & 1] = ss0;
        rowp[m0 + 8 + g][warp & 1] = ss1;
    }
    __syncthreads();
    if (tid < 64) {
        int i = j0 + tid + 63;
        float gate = (i < T_) ? g_gate[((size_t)b * T_ + i) * H_ + h] : 0.f;
        float tot = rowp[tid][0] + rowp[tid][1];
        rscale[tid] = rsqrtf(tot * (1.f / 64.f) + EPSV) * gate;
    }
    __syncthreads();

#pragma unroll
    for (int ni = 0; ni < 4; ni++) {
        int col = n0 + ni * 8 + 2 * tg;
        float ga0 = gam[col], ga1 = gam[col + 1];
#pragma unroll
        for (int half = 0; half < 2; half++) {
            int row = m0 + g + half * 8;
            int i = j0 + row + 63;
            if (i < T_) {
                float rs = rscale[row];
                float v0 = acc[ni][half * 2 + 0] * rs * ga0;
                float v1 = acc[ni][half * 2 + 1] * rs * ga1;
                size_t oidx = ((size_t)b * T_ + i) * DIM2_ + ((h * 64 + col) >> 1);
                g_vhp[oidx] = pack_bf2(v0, v1);
                g_vlp[oidx] = pack_bf2(v0 - bf16f(v0), v1 - bf16f(v1));
            }
        }
    }
}

// ---------------- launch ----------------
extern "C" void kernel_launch(void* const* d_in, const int* in_sizes, int n_in,
                              void* d_out, int out_size) {
    const float* seq      = (const float*)d_in[0];
    const float* w1       = (const float*)d_in[1];
    const float* w2       = (const float*)d_in[2];
    const float* Wq       = (const float*)d_in[3];
    const float* Wkv      = (const float*)d_in[4];
    const float* Wstep    = (const float*)d_in[5];
    const float* Wmom     = (const float*)d_in[6];
    const float* Wdecay   = (const float*)d_in[7];
    const float* Wgate    = (const float*)d_in[8];
    const float* Wcombine = (const float*)d_in[9];
    const float* gamma    = (const float*)d_in[10];
    float* out = (float*)d_out;
    (void)in_sizes; (void)n_in; (void)out_size;

    cudaFuncSetAttribute(gemm_s8, cudaFuncAttributeMaxDynamicSharedMemorySize, SQ_SMEM);
    cudaFuncSetAttribute(gemm_bf16, cudaFuncAttributeMaxDynamicSharedMemorySize, GEMM_SMEM);
    cudaFuncSetAttribute(chunk_grad_tc, cudaFuncAttributeMaxDynamicSharedMemorySize, CG_SMEM);
    cudaFuncSetAttribute(retrieve_tc, cudaFuncAttributeMaxDynamicSharedMemorySize, RT_SMEM);

    uint32_t *p_aqh, *p_aql, *p_vhp, *p_vlp;
    uint32_t *p_wkvqh, *p_wkvql, *p_wqqh, *p_wqql, *p_wch, *p_wcl;
    float *p_asc, *p_wkvsc, *p_wqsc, *p_kv, *p_q;
    cudaGetSymbolAddress((void**)&p_aqh, g_aqh);
    cudaGetSymbolAddress((void**)&p_aql, g_aql);
    cudaGetSymbolAddress((void**)&p_asc, g_asc);
    cudaGetSymbolAddress((void**)&p_vhp, g_vhp);
    cudaGetSymbolAddress((void**)&p_vlp, g_vlp);
    cudaGetSymbolAddress((void**)&p_wkvqh, g_wkvqh);
    cudaGetSymbolAddress((void**)&p_wkvql, g_wkvql);
    cudaGetSymbolAddress((void**)&p_wkvsc, g_wkvsc);
    cudaGetSymbolAddress((void**)&p_wqqh, g_wqqh);
    cudaGetSymbolAddress((void**)&p_wqql, g_wqql);
    cudaGetSymbolAddress((void**)&p_wqsc, g_wqsc);
    cudaGetSymbolAddress((void**)&p_wch, g_wch);
    cudaGetSymbolAddress((void**)&p_wcl, g_wcl);
    cudaGetSymbolAddress((void**)&p_kv, g_kv);
    cudaGetSymbolAddress((void**)&p_q, g_q);

    rmsnorm_kernel<<<B_ * T_, 256>>>(seq);
    wquant_s8<<<2 * DIM_, 128>>>(Wkv, p_wkvqh, p_wkvql, p_wkvsc, 2 * DIM_);
    wquant_s8<<<DIM_, 128>>>(Wq, p_wqqh, p_wqql, p_wqsc, DIM_);
    cvtpack_kernel<<<(DIM2_ * DIM_ + 255) / 256, 256>>>(Wcombine, p_wch, p_wcl, DIM2_, DIM_);
    proj_kernel<<<B_ * N_, 256>>>(Wstep, Wgate, Wmom, Wdecay);
    gemm_s8<<<dim3(2 * DIM_ / 128, B_ * T_ / 128), 512, SQ_SMEM>>>(
        p_aqh, p_aql, p_wkvqh, p_wkvql, p_asc, p_wkvsc, p_kv, 2 * DIM_);
    gemm_s8<<<dim3(DIM_ / 128, B_ * T_ / 128), 512, SQ_SMEM>>>(
        p_aqh, p_aql, p_wqqh, p_wqql, p_asc, p_wqsc, p_q, DIM_);
    chunk_grad_tc<<<BH_ * N_, 256, CG_SMEM>>>(w1, w2);
    scan_kernel<<<dim3(16, BH_), 256>>>(w1, w2);
    zero_pad_kernel<<<(B_ * 63 * DIM2_ + 255) / 256, 256>>>();
    retrieve_tc<<<BH_ * N_, 256, RT_SMEM>>>(gamma);
    gemm_bf16<<<dim3(DIM_ / 128, B_ * T_ / 128), 256, GEMM_SMEM>>>(
        p_vhp, p_vlp, p_wch, p_wcl, out, B_ * T_, DIM_, DIM2_);
}

// round 16
// speedup vs baseline: 1.6697x; 1.6697x over previous
#include <cuda_runtime.h>
#include <cuda_bf16.h>
#include <cstdint>
#include <cstddef>

#define B_ 4
#define T_ 8192
#define DIM_ 512
#define DIM2_ 256
#define H_ 8
#define D_ 64
#define C_ 64
#define N_ 128
#define BH_ 32
#define EPSV 1.1920929e-07f
#define MAX_LR 0.01f

// ---------------- scratch (static device globals; no allocations) ----------------
__device__ float g_s  [(size_t)B_*T_*DIM_];     // rmsnorm(seq) fp32 (for proj)
__device__ uint32_t g_shp[(size_t)B_*T_*DIM2_]; // rmsnorm(seq) bf16x2 hi (k-paired)
__device__ uint32_t g_slp[(size_t)B_*T_*DIM2_]; // bf16x2 lo
__device__ float g_kv [(size_t)B_*T_*2*DIM_];   // [k | v]
__device__ float g_q  [(size_t)B_*T_*DIM_];     // s @ Wq
__device__ float g_g1 [(size_t)BH_*N_*D_*D_];   // -grad w1 -> W1eff after scan
__device__ float g_g2 [(size_t)BH_*N_*D_*D_];   // -grad w2 -> W2eff after scan
__device__ uint32_t g_vhp[(size_t)B_*T_*DIM2_]; // merged vals bf16x2 hi
__device__ uint32_t g_vlp[(size_t)B_*T_*DIM2_]; // bf16x2 lo
__device__ float g_lr  [(size_t)B_*T_*H_];
__device__ float g_gate[(size_t)B_*T_*H_];
__device__ float g_mom [(size_t)B_*N_*H_];
__device__ float g_dec [(size_t)B_*N_*H_];
// preconverted weights, bf16x2 k-paired hi/lo, layout [K2][N]
__device__ uint32_t g_wkvh[DIM2_*2*DIM_], g_wkvl[DIM2_*2*DIM_];
__device__ uint32_t g_wqh [DIM2_*DIM_],   g_wql [DIM2_*DIM_];
__device__ uint32_t g_wch [DIM2_*DIM_],   g_wcl [DIM2_*DIM_];

__device__ __forceinline__ float sigmoidf_(float x) { return 1.f / (1.f + expf(-x)); }

__device__ __forceinline__ uint32_t f2tf(float x) {
    uint32_t r;
    asm("cvt.rna.tf32.f32 %0, %1;" : "=r"(r) : "f"(x));
    return r;
}

__device__ __forceinline__ float bf16f(float x) {
    return __bfloat162float(__float2bfloat16(x));
}

// pack two floats to bf16x2: e0 -> low 16 bits, e1 -> high
__device__ __forceinline__ uint32_t pack_bf2(float e0, float e1) {
    uint32_t r;
    asm("cvt.rn.bf16x2.f32 %0, %1, %2;" : "=r"(r) : "f"(e1), "f"(e0));
    return r;
}

__device__ __forceinline__ void mma_tf32(float c[4], const uint32_t a[4],
                                         uint32_t b0, uint32_t b1) {
    asm volatile(
        "mma.sync.aligned.m16n8k8.row.col.f32.tf32.tf32.f32 "
        "{%0,%1,%2,%3},{%4,%5,%6,%7},{%8,%9},{%0,%1,%2,%3};"
        : "+f"(c[0]), "+f"(c[1]), "+f"(c[2]), "+f"(c[3])
        : "r"(a[0]), "r"(a[1]), "r"(a[2]), "r"(a[3]), "r"(b0), "r"(b1));
}

__device__ __forceinline__ void mma_bf16(float c[4], const uint32_t a[4],
                                         uint32_t b0, uint32_t b1) {
    asm volatile(
        "mma.sync.aligned.m16n8k16.row.col.f32.bf16.bf16.f32 "
        "{%0,%1,%2,%3},{%4,%5,%6,%7},{%8,%9},{%0,%1,%2,%3};"
        : "+f"(c[0]), "+f"(c[1]), "+f"(c[2]), "+f"(c[3])
        : "r"(a[0]), "r"(a[1]), "r"(a[2]), "r"(a[3]), "r"(b0), "r"(b1));
}

__device__ __forceinline__ void cp16(uint32_t dst, const void* src) {
    asm volatile("cp.async.cg.shared.global [%0], [%1], 16;" :: "r"(dst), "l"(src));
}

// ---------------- K1: rmsnorm over dim=512, emits fp32 + packed bf16 hi/lo ----------------
__global__ __launch_bounds__(256) void rmsnorm_kernel(const float* __restrict__ seq) {
    size_t row = blockIdx.x;
    const float2* in2 = (const float2*)(seq + row * DIM_);
    int tid = threadIdx.x;
    float2 v = in2[tid];
    float ss = v.x * v.x + v.y * v.y;
#pragma unroll
    for (int o = 16; o; o >>= 1) ss += __shfl_xor_sync(0xffffffffu, ss, o);
    __shared__ float wsum[8];
    if ((tid & 31) == 0) wsum[tid >> 5] = ss;
    __syncthreads();
    float tot = 0.f;
#pragma unroll
    for (int w = 0; w < 8; w++) tot += wsum[w];
    float sc = rsqrtf(tot * (1.f / DIM_) + EPSV);
    float o0 = v.x * sc, o1 = v.y * sc;
    ((float2*)(g_s + row * DIM_))[tid] = make_float2(o0, o1);
    size_t pb = row * DIM2_ + tid;
    g_shp[pb] = pack_bf2(o0, o1);
    g_slp[pb] = pack_bf2(o0 - bf16f(o0), o1 - bf16f(o1));
}

// ---------------- weight preconvert: pack along K into bf16x2 hi/lo ----------------
__global__ void cvtpack_kernel(const float* __restrict__ src, uint32_t* __restrict__ dh,
                               uint32_t* __restrict__ dl, int K2, int Nc) {
    int i = blockIdx.x * 256 + threadIdx.x;
    if (i < K2 * Nc) {
        int k2 = i / Nc, n = i - k2 * Nc;
        float e0 = src[(size_t)(2 * k2) * Nc + n];
        float e1 = src[(size_t)(2 * k2 + 1) * Nc + n];
        dh[i] = pack_bf2(e0, e1);
        dl[i] = pack_bf2(e0 - bf16f(e0), e1 - bf16f(e1));
    }
}

// ---------------- K2: per-token lr/gate projections + per-chunk mom/decay ----------------
__global__ __launch_bounds__(256) void proj_kernel(const float* __restrict__ Wstep,
                                                   const float* __restrict__ Wgate,
                                                   const float* __restrict__ Wmom,
                                                   const float* __restrict__ Wdecay) {
    int blk = blockIdx.x;              // b*N_ + nn
    int b = blk >> 7, nn = blk & 127;
    size_t tb = (size_t)b * T_ + (size_t)nn * C_;
    int tid = threadIdx.x, lane = tid & 31, w = tid >> 5;

    for (int tk = w; tk < C_; tk += 8) {
        const float* srow = g_s + (tb + tk) * DIM_;
        float acc[16];
#pragma unroll
        for (int q = 0; q < 16; q++) acc[q] = 0.f;
        for (int p = lane; p < DIM_; p += 32) {
            float sv = srow[p];
            const float* ws = Wstep + p * H_;
            const float* wg = Wgate + p * H_;
#pragma unroll
            for (int hh = 0; hh < 8; hh++) {
                acc[hh]     += sv * ws[hh];
                acc[8 + hh] += sv * wg[hh];
            }
        }
#pragma unroll
        for (int q = 0; q < 16; q++)
#pragma unroll
            for (int o = 16; o; o >>= 1) acc[q] += __shfl_xor_sync(0xffffffffu, acc[q], o);
        if (lane == 0) {
#pragma unroll
            for (int hh = 0; hh < 8; hh++) {
                g_lr  [(tb + tk) * H_ + hh] = sigmoidf_(acc[hh]) * MAX_LR;
                g_gate[(tb + tk) * H_ + hh] = sigmoidf_(acc[8 + hh]);
            }
        }
    }

    __shared__ float ssum[DIM_];
    for (int p = tid; p < DIM_; p += 256) {
        float a = 0.f;
        for (int tk = 0; tk < C_; tk++) a += g_s[(tb + tk) * DIM_ + p];
        ssum[p] = a * (1.f / C_);
    }
    __syncthreads();
    if (w < 8) {
        float am = 0.f, ad = 0.f;
        for (int p = lane; p < DIM_; p += 32) {
            am += ssum[p] * Wmom[p * H_ + w];
            ad += ssum[p] * Wdecay[p * H_ + w];
        }
#pragma unroll
        for (int o = 16; o; o >>= 1) {
            am += __shfl_xor_sync(0xffffffffu, am, o);
            ad += __shfl_xor_sync(0xffffffffu, ad, o);
        }
        if (lane == 0) {
            g_mom[((size_t)b * N_ + nn) * H_ + w] = sigmoidf_(am);
            g_dec[((size_t)b * N_ + nn) * H_ + w] = sigmoidf_(ad);
        }
    }
}

// ---------------- gemm_bf16: cp.async double-buffered bf16 split ----------------
// TERM3: true = ah*bh + ah*bl + al*bh (3-term); false = ah*bh + ah*bl (A hi only)
// A packed [M][K2] u32 (bf16x2 along k), B packed [K2][N] u32, C fp32 [M][N]
#define GA_LD 20
#define GB_LD 136
#define GA_SZ (128 * GA_LD)
#define GB_SZ (16 * GB_LD)
#define GSTAGE (2 * GA_SZ + 2 * GB_SZ)
#define GEMM_SMEM (2 * GSTAGE * 4)

template <bool TERM3>
__device__ __forceinline__ void gemm_issue(uint32_t sbase, const uint32_t* __restrict__ Ah,
                                           const uint32_t* __restrict__ Al,
                                           const uint32_t* __restrict__ Bh,
                                           const uint32_t* __restrict__ Bl,
                                           int brow, int bcol, int kt2, int K2, int Nc, int tid) {
    int ra = tid >> 2, ca = (tid & 3) << 2;
    int rb = tid >> 5, cb = (tid & 31) << 2;
#pragma unroll
    for (int p = 0; p < 2; p++) {
        int r = p * 64 + ra;
        size_t ga = (size_t)(brow + r) * K2 + kt2 + ca;
        uint32_t da = sbase + (r * GA_LD + ca) * 4;
        cp16(da, Ah + ga);
        if (TERM3) cp16(da + GA_SZ * 4, Al + ga);
        int r2 = p * 8 + rb;
        size_t gb = (size_t)(kt2 + r2) * Nc + bcol + cb;
        uint32_t db = sbase + (2 * GA_SZ + r2 * GB_LD + cb) * 4;
        cp16(db, Bh + gb);
        cp16(db + GB_SZ * 4, Bl + gb);
    }
}

template <bool TERM3>
__global__ __launch_bounds__(256, 2) void gemm_bf16(const uint32_t* __restrict__ Ah,
                                                    const uint32_t* __restrict__ Al,
                                                    const uint32_t* __restrict__ Bh,
                                                    const uint32_t* __restrict__ Bl,
                                                    float* __restrict__ C,
                                                    int M, int Nc, int K2) {
    extern __shared__ uint32_t smem_u[];
    int tid = threadIdx.x;
    int lane = tid & 31, warp = tid >> 5;
    int brow = blockIdx.y * 128, bcol = blockIdx.x * 128;
    int wm = (warp >> 1) * 32, wn = (warp & 1) * 64;
    int g = lane >> 2, tg = lane & 3;
    uint32_t sbase = (uint32_t)__cvta_generic_to_shared(smem_u);

    float acc[2][8][4];
#pragma unroll
    for (int mi = 0; mi < 2; mi++)
#pragma unroll
        for (int ni = 0; ni < 8; ni++)
#pragma unroll
            for (int e = 0; e < 4; e++) acc[mi][ni][e] = 0.f;

    gemm_issue<TERM3>(sbase, Ah, Al, Bh, Bl, brow, bcol, 0, K2, Nc, tid);
    asm volatile("cp.async.commit_group;");

    int KT = K2 >> 4;
    for (int t = 0; t < KT; t++) {
        if (t + 1 < KT) {
            gemm_issue<TERM3>(sbase + ((t + 1) & 1) * GSTAGE * 4, Ah, Al, Bh, Bl,
                              brow, bcol, (t + 1) << 4, K2, Nc, tid);
            asm volatile("cp.async.commit_group;");
            asm volatile("cp.async.wait_group 1;");
        } else {
            asm volatile("cp.async.wait_group 0;");
        }
        __syncthreads();
        const uint32_t* st = smem_u + (t & 1) * GSTAGE;
        const uint32_t* sAh = st;
        const uint32_t* sAl = st + GA_SZ;
        const uint32_t* sBh = st + 2 * GA_SZ;
        const uint32_t* sBl = st + 2 * GA_SZ + GB_SZ;
#pragma unroll
        for (int kh = 0; kh < 2; kh++) {
            int k8 = kh * 8;
            uint32_t ah[2][4], al[2][4];
#pragma unroll
            for (int mi = 0; mi < 2; mi++) {
                int r0 = (wm + mi * 16 + g) * GA_LD + k8 + tg;
                int r1 = r0 + 8 * GA_LD;
                ah[mi][0] = sAh[r0];     ah[mi][1] = sAh[r1];
                ah[mi][2] = sAh[r0 + 4]; ah[mi][3] = sAh[r1 + 4];
                if (TERM3) {
                    al[mi][0] = sAl[r0];     al[mi][1] = sAl[r1];
                    al[mi][2] = sAl[r0 + 4]; al[mi][3] = sAl[r1 + 4];
                }
            }
#pragma unroll
            for (int ni = 0; ni < 8; ni++) {
                int nb = (k8 + tg) * GB_LD + wn + ni * 8 + g;
                uint32_t bh0 = sBh[nb], bh1 = sBh[nb + 4 * GB_LD];
                uint32_t bl0 = sBl[nb], bl1 = sBl[nb + 4 * GB_LD];
#pragma unroll
                for (int mi = 0; mi < 2; mi++) {
                    mma_bf16(acc[mi][ni], ah[mi], bh0, bh1);
                    mma_bf16(acc[mi][ni], ah[mi], bl0, bl1);
                    if (TERM3) mma_bf16(acc[mi][ni], al[mi], bh0, bh1);
                }
            }
        }
        __syncthreads();
    }

#pragma unroll
    for (int mi = 0; mi < 2; mi++)
#pragma unroll
        for (int ni = 0; ni < 8; ni++) {
            int r = brow + wm + mi * 16 + g;
            int cx = bcol + wn + ni * 8 + tg * 2;
            float2 lo = {acc[mi][ni][0], acc[mi][ni][1]};
            float2 hi = {acc[mi][ni][2], acc[mi][ni][3]};
            *(float2*)(C + (size_t)r * Nc + cx) = lo;
            *(float2*)(C + (size_t)(r + 8) * Nc + cx) = hi;
        }
}

// ---------------- tensor-core 64x64x64 from smem tf32 hi/lo, selectable terms ----------------
#define CLD 68
#define BUF (64 * CLD)

template <bool TA, bool TB, bool AL, bool BL>
__device__ __forceinline__ void mm64_tc(const uint32_t* __restrict__ Ah,
                                        const uint32_t* __restrict__ Al,
                                        const uint32_t* __restrict__ Bh,
                                        const uint32_t* __restrict__ Bl,
                                        float acc[4][4], int m0, int n0, int g, int tg) {
#pragma unroll
    for (int ni = 0; ni < 4; ni++)
#pragma unroll
        for (int e = 0; e < 4; e++) acc[ni][e] = 0.f;
#pragma unroll 2
    for (int k8 = 0; k8 < 64; k8 += 8) {
        uint32_t ah[4], al[4] = {0, 0, 0, 0};
        if (!TA) {
            int ba = (m0 + g) * CLD + k8 + tg;
            ah[0] = Ah[ba]; ah[1] = Ah[ba + 8 * CLD]; ah[2] = Ah[ba + 4]; ah[3] = Ah[ba + 8 * CLD + 4];
            if (AL) {
                al[0] = Al[ba]; al[1] = Al[ba + 8 * CLD]; al[2] = Al[ba + 4]; al[3] = Al[ba + 8 * CLD + 4];
            }
        } else {
            int ba = (k8 + tg) * CLD + m0 + g;
            ah[0] = Ah[ba]; ah[1] = Ah[ba + 8]; ah[2] = Ah[ba + 4 * CLD]; ah[3] = Ah[ba + 4 * CLD + 8];
            if (AL) {
                al[0] = Al[ba]; al[1] = Al[ba + 8]; al[2] = Al[ba + 4 * CLD]; al[3] = Al[ba + 4 * CLD + 8];
            }
        }
#pragma unroll
        for (int ni = 0; ni < 4; ni++) {
            uint32_t bh0, bh1, bl0 = 0, bl1 = 0;
            if (!TB) {
                int bb = (k8 + tg) * CLD + n0 + ni * 8 + g;
                bh0 = Bh[bb]; bh1 = Bh[bb + 4 * CLD];
                if (BL) { bl0 = Bl[bb]; bl1 = Bl[bb + 4 * CLD]; }
            } else {
                int bb = (n0 + ni * 8 + g) * CLD + k8 + tg;
                bh0 = Bh[bb]; bh1 = Bh[bb + 4];
                if (BL) { bl0 = Bl[bb]; bl1 = Bl[bb + 4]; }
            }
            mma_tf32(acc[ni], ah, bh0, bh1);
            if (BL) mma_tf32(acc[ni], ah, bl0, bl1);
            if (AL) mma_tf32(acc[ni], al, bh0, bh1);
        }
    }
}

// fragment (row, col): e0=(g,2tg) e1=(g,2tg+1) e2=(g+8,2tg) e3=(g+8,2tg+1)
#define FRAG_ROW(e) (m0 + g + ((e) >> 1 ? 8 : 0))
#define FRAG_COL(ni, e) (n0 + (ni) * 8 + 2 * tg + ((e) & 1))

// ---------------- K4: per-chunk MLP gradients (6 smem bufs -> 2 CTAs/SM) ----------------
#define CG_SMEM (6 * BUF * 4)
__global__ __launch_bounds__(256, 2) void chunk_grad_tc(const float* __restrict__ w1,
                                                        const float* __restrict__ w2) {
    int id = blockIdx.x;               // bh*N_ + nn
    int bh = id >> 7, nn = id & 127;
    int b = bh >> 3, h = bh & 7;
    size_t tb = (size_t)b * T_ + (size_t)nn * C_;
    extern __shared__ uint32_t smu2[];
    uint32_t* KCh = smu2;
    uint32_t* HHh = smu2 + BUF;
    uint32_t* HHl = smu2 + 2 * BUF;
    uint32_t* W2h = smu2 + 3 * BUF;
    uint32_t* W2l = smu2 + 4 * BUF;
    uint32_t* G2h = smu2 + 5 * BUF;
    __shared__ float lrs[64];
    int tid = threadIdx.x;
    if (tid < 64) lrs[tid] = g_lr[(tb + tid) * H_ + h];
    for (int idx = tid; idx < 4096; idx += 256) {
        int i = idx >> 6, j = idx & 63;
        float kc = g_kv[(tb + i) * (2 * DIM_) + h * 64 + j];
        KCh[i * CLD + j] = f2tf(kc);
        float a1 = w1[idx];
        uint32_t hi = f2tf(a1);
        HHh[i * CLD + j] = hi; HHl[i * CLD + j] = f2tf(a1 - __uint_as_float(hi));
        float a2 = w2[idx];
        hi = f2tf(a2);
        W2h[i * CLD + j] = hi; W2l[i * CLD + j] = f2tf(a2 - __uint_as_float(hi));
    }
    __syncthreads();
    int lane = tid & 31, warp = tid >> 5;
    int m0 = (warp >> 1) * 16, n0 = (warp & 1) * 32;
    int g = lane >> 2, tg = lane & 3;
    float acc[4][4], x1s[4][4];

    // MM1: X1 = KC(hi) @ W1(hi/lo); X1 in regs; HH = silu(X1) hi/lo
    mm64_tc<false, false, false, true>(KCh, nullptr, HHh, HHl, acc, m0, n0, g, tg);
    __syncthreads();
#pragma unroll
    for (int ni = 0; ni < 4; ni++)
#pragma unroll
        for (int e = 0; e < 4; e++) {
            int row = FRAG_ROW(e), col = FRAG_COL(ni, e);
            float x = acc[ni][e];
            x1s[ni][e] = x;
            float hv = x * sigmoidf_(x);
            uint32_t hi = f2tf(hv);
            HHh[row * CLD + col] = hi;
            HHl[row * CLD + col] = f2tf(hv - __uint_as_float(hi));
        }
    __syncthreads();

    // MM2: X2 = HH @ W2 [3-term] ; G2 hi only
    mm64_tc<false, false, true, true>(HHh, HHl, W2h, W2l, acc, m0, n0, g, tg);
#pragma unroll
    for (int ni = 0; ni < 4; ni++)
#pragma unroll
        for (int e = 0; e < 4; e++) {
            int row = FRAG_ROW(e), col = FRAG_COL(ni, e);
            float vc = g_kv[(tb + row) * (2 * DIM_) + DIM_ + h * 64 + col];
            float gg = (2.f / 64.f) * lrs[row] * (acc[ni][e] - vc);
            G2h[row * CLD + col] = f2tf(gg);
        }
    __syncthreads();

    // MM3: g2 = HH^T @ G2(hi) -> -g2
    mm64_tc<true, false, true, false>(HHh, HHl, G2h, nullptr, acc, m0, n0, g, tg);
    size_t gbase = (size_t)id * 4096;
#pragma unroll
    for (int ni = 0; ni < 4; ni++) {
        int col = n0 + ni * 8 + 2 * tg;
        float2 v0 = {-acc[ni][0], -acc[ni][1]};
        float2 v1 = {-acc[ni][2], -acc[ni][3]};
        *(float2*)(g_g2 + gbase + (m0 + g) * 64 + col) = v0;
        *(float2*)(g_g2 + gbase + (m0 + 8 + g) * 64 + col) = v1;
    }
    __syncthreads();

    // MM4: DX1 = (G2(hi) @ W2^T) * silu'(X1) -> HH bufs
    mm64_tc<false, true, false, true>(G2h, nullptr, W2h, W2l, acc, m0, n0, g, tg);
#pragma unroll
    for (int ni = 0; ni < 4; ni++)
#pragma unroll
        for (int e = 0; e < 4; e++) {
            int row = FRAG_ROW(e), col = FRAG_COL(ni, e);
            float x = x1s[ni][e];
            float sg = sigmoidf_(x);
            float dv = acc[ni][e] * sg * (1.f + x * (1.f - sg));
            uint32_t hi = f2tf(dv);
            HHh[row * CLD + col] = hi;
            HHl[row * CLD + col] = f2tf(dv - __uint_as_float(hi));
        }
    __syncthreads();

    // MM5: g1 = KC^T(hi) @ DX1 -> -g1
    mm64_tc<true, false, false, true>(KCh, nullptr, HHh, HHl, acc, m0, n0, g, tg);
#pragma unroll
    for (int ni = 0; ni < 4; ni++) {
        int col = n0 + ni * 8 + 2 * tg;
        float2 v0 = {-acc[ni][0], -acc[ni][1]};
        float2 v1 = {-acc[ni][2], -acc[ni][3]};
        *(float2*)(g_g1 + gbase + (m0 + g) * 64 + col) = v0;
        *(float2*)(g_g1 + gbase + (m0 + 8 + g) * 64 + col) = v1;
    }
}

// ---------------- K5: double assoc-scan over n=128 chunks ----------------
__global__ __launch_bounds__(256) void scan_kernel(const float* __restrict__ w1,
                                                   const float* __restrict__ w2) {
    int bh = blockIdx.y;
    int idx = blockIdx.x * 256 + threadIdx.x;
    int b = bh >> 3, h = bh & 7;
    float w1v = w1[idx], w2v = w2[idx];
    float m1 = 0.f, u1 = 0.f, m2 = 0.f, u2 = 0.f;
    size_t base = ((size_t)bh * N_) * 4096 + idx;
    for (int nn = 0; nn < N_; nn++) {
        float mg = g_mom[((size_t)b * N_ + nn) * H_ + h];
        float dc = g_dec[((size_t)b * N_ + nn) * H_ + h];
        size_t off = base + (size_t)nn * 4096;
        float s1 = g_g1[off], s2 = g_g2[off];
        m1 = mg * m1 + s1; u1 = (1.f - dc) * u1 + m1; g_g1[off] = w1v + u1;
        m2 = mg * m2 + s2; u2 = (1.f - dc) * u2 + m2; g_g2[off] = w2v + u2;
    }
}

// ---------------- zero first 63 rows of packed vals per batch ----------------
__global__ void zero_pad_kernel() {
    int idx = blockIdx.x * 256 + threadIdx.x;
    const int per = 63 * DIM2_;
    if (idx < B_ * per) {
        int b = idx / per, r = idx % per;
        g_vhp[(size_t)b * T_ * DIM2_ + r] = 0u;
        g_vlp[(size_t)b * T_ * DIM2_ + r] = 0u;
    }
}

// ---------------- K6: retrieve (tensor cores, 3x tf32; emits packed bf16 vals) ----------------
#define RT_SMEM (6 * BUF * 4)
__global__ __launch_bounds__(256, 2) void retrieve_tc(const float* __restrict__ gamma) {
    int id = blockIdx.x;
    int bh = id >> 7, nn = id & 127;
    int b = bh >> 3, h = bh & 7;
    extern __shared__ uint32_t smu3[];
    uint32_t* Qh  = smu3;
    uint32_t* Ql  = smu3 + BUF;
    uint32_t* HHh = smu3 + 2 * BUF;   // W1eff first, then HH
    uint32_t* HHl = smu3 + 3 * BUF;
    uint32_t* W2h = smu3 + 4 * BUF;
    uint32_t* W2l = smu3 + 5 * BUF;
    __shared__ float rowp[64][2];
    __shared__ float gam[64];
    __shared__ float rscale[64];
    int tid = threadIdx.x;
    int j0 = nn * C_;
    size_t gbase = (size_t)id * 4096;
    if (tid < 64) gam[tid] = gamma[h * 64 + tid] + 1.f;
    for (int idx = tid; idx < 4096; idx += 256) {
        int ci = idx >> 6, a = idx & 63;
        int i = j0 + ci + 63;
        float qv = (i < T_) ? g_q[((size_t)b * T_ + i) * DIM_ + h * 64 + a] : 0.f;
        uint32_t hi = f2tf(qv);
        Qh[ci * CLD + a] = hi; Ql[ci * CLD + a] = f2tf(qv - __uint_as_float(hi));
        float e1 = g_g1[gbase + idx];
        hi = f2tf(e1);
        HHh[ci * CLD + a] = hi; HHl[ci * CLD + a] = f2tf(e1 - __uint_as_float(hi));
        float e2 = g_g2[gbase + idx];
        hi = f2tf(e2);
        W2h[ci * CLD + a] = hi; W2l[ci * CLD + a] = f2tf(e2 - __uint_as_float(hi));
    }
    __syncthreads();
    int lane = tid & 31, warp = tid >> 5;
    int m0 = (warp >> 1) * 16, n0 = (warp & 1) * 32;
    int g = lane >> 2, tg = lane & 3;
    float acc[4][4];

    mm64_tc<false, false, true, true>(Qh, Ql, HHh, HHl, acc, m0, n0, g, tg);
    __syncthreads();
#pragma unroll
    for (int ni = 0; ni < 4; ni++)
#pragma unroll
        for (int e = 0; e < 4; e++) {
            int row = FRAG_ROW(e), col = FRAG_COL(ni, e);
            float x = acc[ni][e];
            float hv = x * sigmoidf_(x);
            uint32_t hi = f2tf(hv);
            HHh[row * CLD + col] = hi;
            HHl[row * CLD + col] = f2tf(hv - __uint_as_float(hi));
        }
    __syncthreads();

    mm64_tc<false, false, true, true>(HHh, HHl, W2h, W2l, acc, m0, n0, g, tg);

    float ss0 = 0.f, ss1 = 0.f;
#pragma unroll
    for (int ni = 0; ni < 4; ni++) {
        ss0 += acc[ni][0] * acc[ni][0] + acc[ni][1] * acc[ni][1];
        ss1 += acc[ni][2] * acc[ni][2] + acc[ni][3] * acc[ni][3];
    }
#pragma unroll
    for (int o = 1; o < 4; o <<= 1) {
        ss0 += __shfl_xor_sync(0xffffffffu, ss0, o);
        ss1 += __shfl_xor_sync(0xffffffffu, ss1, o);
    }
    if (tg == 0) {
        rowp[m0 + g][warp & 1] = ss0;
        rowp[m0 + 8 + g][warp & 1] = ss1;
    }
    __syncthreads();
    if (tid < 64) {
        int i = j0 + tid + 63;
        float gate = (i < T_) ? g_gate[((size_t)b * T_ + i) * H_ + h] : 0.f;
        float tot = rowp[tid][0] + rowp[tid][1];
        rscale[tid] = rsqrtf(tot * (1.f / 64.f) + EPSV) * gate;
    }
    __syncthreads();

#pragma unroll
    for (int ni = 0; ni < 4; ni++) {
        int col = n0 + ni * 8 + 2 * tg;
        float ga0 = gam[col], ga1 = gam[col + 1];
#pragma unroll
        for (int half = 0; half < 2; half++) {
            int row = m0 + g + half * 8;
            int i = j0 + row + 63;
            if (i < T_) {
                float rs = rscale[row];
                float v0 = acc[ni][half * 2 + 0] * rs * ga0;
                float v1 = acc[ni][half * 2 + 1] * rs * ga1;
                size_t oidx = ((size_t)b * T_ + i) * DIM2_ + ((h * 64 + col) >> 1);
                g_vhp[oidx] = pack_bf2(v0, v1);
                g_vlp[oidx] = pack_bf2(v0 - bf16f(v0), v1 - bf16f(v1));
            }
        }
    }
}

// ---------------- launch ----------------
extern "C" void kernel_launch(void* const* d_in, const int* in_sizes, int n_in,
                              void* d_out, int out_size) {
    const float* seq      = (const float*)d_in[0];
    const float* w1       = (const float*)d_in[1];
    const float* w2       = (const float*)d_in[2];
    const float* Wq       = (const float*)d_in[3];
    const float* Wkv      = (const float*)d_in[4];
    const float* Wstep    = (const float*)d_in[5];
    const float* Wmom     = (const float*)d_in[6];
    const float* Wdecay   = (const float*)d_in[7];
    const float* Wgate    = (const float*)d_in[8];
    const float* Wcombine = (const float*)d_in[9];
    const float* gamma    = (const float*)d_in[10];
    float* out = (float*)d_out;
    (void)in_sizes; (void)n_in; (void)out_size;

    cudaFuncSetAttribute(gemm_bf16<true>, cudaFuncAttributeMaxDynamicSharedMemorySize, GEMM_SMEM);
    cudaFuncSetAttribute(gemm_bf16<false>, cudaFuncAttributeMaxDynamicSharedMemorySize, GEMM_SMEM);
    cudaFuncSetAttribute(chunk_grad_tc, cudaFuncAttributeMaxDynamicSharedMemorySize, CG_SMEM);
    cudaFuncSetAttribute(retrieve_tc, cudaFuncAttributeMaxDynamicSharedMemorySize, RT_SMEM);

    uint32_t *p_shp, *p_slp, *p_vhp, *p_vlp;
    uint32_t *p_wkvh, *p_wkvl, *p_wqh, *p_wql, *p_wch, *p_wcl;
    float *p_kv, *p_q;
    cudaGetSymbolAddress((void**)&p_shp, g_shp);
    cudaGetSymbolAddress((void**)&p_slp, g_slp);
    cudaGetSymbolAddress((void**)&p_vhp, g_vhp);
    cudaGetSymbolAddress((void**)&p_vlp, g_vlp);
    cudaGetSymbolAddress((void**)&p_wkvh, g_wkvh);
    cudaGetSymbolAddress((void**)&p_wkvl, g_wkvl);
    cudaGetSymbolAddress((void**)&p_wqh, g_wqh);
    cudaGetSymbolAddress((void**)&p_wql, g_wql);
    cudaGetSymbolAddress((void**)&p_wch, g_wch);
    cudaGetSymbolAddress((void**)&p_wcl, g_wcl);
    cudaGetSymbolAddress((void**)&p_kv, g_kv);
    cudaGetSymbolAddress((void**)&p_q, g_q);

    rmsnorm_kernel<<<B_ * T_, 256>>>(seq);
    cvtpack_kernel<<<(DIM2_ * 2 * DIM_ + 255) / 256, 256>>>(Wkv, p_wkvh, p_wkvl, DIM2_, 2 * DIM_);
    cvtpack_kernel<<<(DIM2_ * DIM_ + 255) / 256, 256>>>(Wq, p_wqh, p_wql, DIM2_, DIM_);
    cvtpack_kernel<<<(DIM2_ * DIM_ + 255) / 256, 256>>>(Wcombine, p_wch, p_wcl, DIM2_, DIM_);
    proj_kernel<<<B_ * N_, 256>>>(Wstep, Wgate, Wmom, Wdecay);
    // Wkv: 2-term (store path, error dampened through grads/scan)
    gemm_bf16<false><<<dim3(2 * DIM_ / 128, B_ * T_ / 128), 256, GEMM_SMEM>>>(
        p_shp, p_slp, p_wkvh, p_wkvl, p_kv, B_ * T_, 2 * DIM_, DIM2_);
    // Wq: 3-term (feeds retrieve directly)
    gemm_bf16<true><<<dim3(DIM_ / 128, B_ * T_ / 128), 256, GEMM_SMEM>>>(
        p_shp, p_slp, p_wqh, p_wql, p_q, B_ * T_, DIM_, DIM2_);
    chunk_grad_tc<<<BH_ * N_, 256, CG_SMEM>>>(w1, w2);
    scan_kernel<<<dim3(16, BH_), 256>>>(w1, w2);
    zero_pad_kernel<<<(B_ * 63 * DIM2_ + 255) / 256, 256>>>();
    retrieve_tc<<<BH_ * N_, 256, RT_SMEM>>>(gamma);
    // out: 3-term (output path)
    gemm_bf16<true><<<dim3(DIM_ / 128, B_ * T_ / 128), 256, GEMM_SMEM>>>(
        p_vhp, p_vlp, p_wch, p_wcl, out, B_ * T_, DIM_, DIM2_);
}

// round 17
// speedup vs baseline: 1.8428x; 1.1037x over previous
#include <cuda_runtime.h>
#include <cuda_bf16.h>
#include <cstdint>
#include <cstddef>

#define B_ 4
#define T_ 8192
#define DIM_ 512
#define DIM2_ 256
#define H_ 8
#define D_ 64
#define C_ 64
#define N_ 128
#define BH_ 32
#define EPSV 1.1920929e-07f
#define MAX_LR 0.01f

// ---------------- scratch (static device globals; no allocations) ----------------
__device__ float g_s  [(size_t)B_*T_*DIM_];     // rmsnorm(seq) fp32 (for proj)
__device__ uint32_t g_shp[(size_t)B_*T_*DIM2_]; // rmsnorm(seq) bf16x2 hi (k-paired)
__device__ uint32_t g_slp[(size_t)B_*T_*DIM2_]; // bf16x2 lo
__device__ float g_kv [(size_t)B_*T_*2*DIM_];   // [k | v]
__device__ float g_q  [(size_t)B_*T_*DIM_];     // s @ Wq
__device__ float g_g1 [(size_t)BH_*N_*D_*D_];   // -grad w1 -> W1eff after scan
__device__ float g_g2 [(size_t)BH_*N_*D_*D_];   // -grad w2 -> W2eff after scan
__device__ uint32_t g_vhp[(size_t)B_*T_*DIM2_]; // merged vals bf16x2 hi
__device__ uint32_t g_vlp[(size_t)B_*T_*DIM2_]; // bf16x2 lo
__device__ float g_lr  [(size_t)B_*T_*H_];
__device__ float g_gate[(size_t)B_*T_*H_];
__device__ float g_mom [(size_t)B_*N_*H_];
__device__ float g_dec [(size_t)B_*N_*H_];
// preconverted weights, bf16x2 k-paired hi/lo, layout [K2][N]
__device__ uint32_t g_wkvh[DIM2_*2*DIM_], g_wkvl[DIM2_*2*DIM_];
__device__ uint32_t g_wqh [DIM2_*DIM_],   g_wql [DIM2_*DIM_];
__device__ uint32_t g_wch [DIM2_*DIM_],   g_wcl [DIM2_*DIM_];

__device__ __forceinline__ float sigmoidf_(float x) { return 1.f / (1.f + expf(-x)); }

__device__ __forceinline__ uint32_t f2tf(float x) {
    uint32_t r;
    asm("cvt.rna.tf32.f32 %0, %1;" : "=r"(r) : "f"(x));
    return r;
}

__device__ __forceinline__ float bf16f(float x) {
    return __bfloat162float(__float2bfloat16(x));
}

// pack two floats to bf16x2: e0 -> low 16 bits, e1 -> high
__device__ __forceinline__ uint32_t pack_bf2(float e0, float e1) {
    uint32_t r;
    asm("cvt.rn.bf16x2.f32 %0, %1, %2;" : "=r"(r) : "f"(e1), "f"(e0));
    return r;
}

__device__ __forceinline__ void mma_tf32(float c[4], const uint32_t a[4],
                                         uint32_t b0, uint32_t b1) {
    asm volatile(
        "mma.sync.aligned.m16n8k8.row.col.f32.tf32.tf32.f32 "
        "{%0,%1,%2,%3},{%4,%5,%6,%7},{%8,%9},{%0,%1,%2,%3};"
        : "+f"(c[0]), "+f"(c[1]), "+f"(c[2]), "+f"(c[3])
        : "r"(a[0]), "r"(a[1]), "r"(a[2]), "r"(a[3]), "r"(b0), "r"(b1));
}

__device__ __forceinline__ void mma_bf16(float c[4], const uint32_t a[4],
                                         uint32_t b0, uint32_t b1) {
    asm volatile(
        "mma.sync.aligned.m16n8k16.row.col.f32.bf16.bf16.f32 "
        "{%0,%1,%2,%3},{%4,%5,%6,%7},{%8,%9},{%0,%1,%2,%3};"
        : "+f"(c[0]), "+f"(c[1]), "+f"(c[2]), "+f"(c[3])
        : "r"(a[0]), "r"(a[1]), "r"(a[2]), "r"(a[3]), "r"(b0), "r"(b1));
}

__device__ __forceinline__ void cp16(uint32_t dst, const void* src) {
    asm volatile("cp.async.cg.shared.global [%0], [%1], 16;" :: "r"(dst), "l"(src));
}

// ---------------- K1: rmsnorm over dim=512, emits fp32 + packed bf16 hi/lo ----------------
__global__ __launch_bounds__(256) void rmsnorm_kernel(const float* __restrict__ seq) {
    size_t row = blockIdx.x;
    const float2* in2 = (const float2*)(seq + row * DIM_);
    int tid = threadIdx.x;
    float2 v = in2[tid];
    float ss = v.x * v.x + v.y * v.y;
#pragma unroll
    for (int o = 16; o; o >>= 1) ss += __shfl_xor_sync(0xffffffffu, ss, o);
    __shared__ float wsum[8];
    if ((tid & 31) == 0) wsum[tid >> 5] = ss;
    __syncthreads();
    float tot = 0.f;
#pragma unroll
    for (int w = 0; w < 8; w++) tot += wsum[w];
    float sc = rsqrtf(tot * (1.f / DIM_) + EPSV);
    float o0 = v.x * sc, o1 = v.y * sc;
    ((float2*)(g_s + row * DIM_))[tid] = make_float2(o0, o1);
    size_t pb = row * DIM2_ + tid;
    g_shp[pb] = pack_bf2(o0, o1);
    g_slp[pb] = pack_bf2(o0 - bf16f(o0), o1 - bf16f(o1));
}

// ---------------- weight preconvert: pack along K into bf16x2 hi/lo ----------------
__global__ void cvtpack_kernel(const float* __restrict__ src, uint32_t* __restrict__ dh,
                               uint32_t* __restrict__ dl, int K2, int Nc) {
    int i = blockIdx.x * 256 + threadIdx.x;
    if (i < K2 * Nc) {
        int k2 = i / Nc, n = i - k2 * Nc;
        float e0 = src[(size_t)(2 * k2) * Nc + n];
        float e1 = src[(size_t)(2 * k2 + 1) * Nc + n];
        dh[i] = pack_bf2(e0, e1);
        dl[i] = pack_bf2(e0 - bf16f(e0), e1 - bf16f(e1));
    }
}

// ---------------- K2: per-token lr/gate projections + per-chunk mom/decay ----------------
__global__ __launch_bounds__(256) void proj_kernel(const float* __restrict__ Wstep,
                                                   const float* __restrict__ Wgate,
                                                   const float* __restrict__ Wmom,
                                                   const float* __restrict__ Wdecay) {
    int blk = blockIdx.x;              // b*N_ + nn
    int b = blk >> 7, nn = blk & 127;
    size_t tb = (size_t)b * T_ + (size_t)nn * C_;
    int tid = threadIdx.x, lane = tid & 31, w = tid >> 5;

    for (int tk = w; tk < C_; tk += 8) {
        const float* srow = g_s + (tb + tk) * DIM_;
        float acc[16];
#pragma unroll
        for (int q = 0; q < 16; q++) acc[q] = 0.f;
        for (int p = lane; p < DIM_; p += 32) {
            float sv = srow[p];
            const float* ws = Wstep + p * H_;
            const float* wg = Wgate + p * H_;
#pragma unroll
            for (int hh = 0; hh < 8; hh++) {
                acc[hh]     += sv * ws[hh];
                acc[8 + hh] += sv * wg[hh];
            }
        }
#pragma unroll
        for (int q = 0; q < 16; q++)
#pragma unroll
            for (int o = 16; o; o >>= 1) acc[q] += __shfl_xor_sync(0xffffffffu, acc[q], o);
        if (lane == 0) {
#pragma unroll
            for (int hh = 0; hh < 8; hh++) {
                g_lr  [(tb + tk) * H_ + hh] = sigmoidf_(acc[hh]) * MAX_LR;
                g_gate[(tb + tk) * H_ + hh] = sigmoidf_(acc[8 + hh]);
            }
        }
    }

    __shared__ float ssum[DIM_];
    for (int p = tid; p < DIM_; p += 256) {
        float a = 0.f;
        for (int tk = 0; tk < C_; tk++) a += g_s[(tb + tk) * DIM_ + p];
        ssum[p] = a * (1.f / C_);
    }
    __syncthreads();
    if (w < 8) {
        float am = 0.f, ad = 0.f;
        for (int p = lane; p < DIM_; p += 32) {
            am += ssum[p] * Wmom[p * H_ + w];
            ad += ssum[p] * Wdecay[p * H_ + w];
        }
#pragma unroll
        for (int o = 16; o; o >>= 1) {
            am += __shfl_xor_sync(0xffffffffu, am, o);
            ad += __shfl_xor_sync(0xffffffffu, ad, o);
        }
        if (lane == 0) {
            g_mom[((size_t)b * N_ + nn) * H_ + w] = sigmoidf_(am);
            g_dec[((size_t)b * N_ + nn) * H_ + w] = sigmoidf_(ad);
        }
    }
}

// ---------------- gemm_bf16: cp.async double-buffered bf16 split ----------------
// TERM3: true = ah*bh + ah*bl + al*bh (3-term); false = ah*bh + ah*bl (A hi only)
#define GA_LD 20
#define GB_LD 136
#define GA_SZ (128 * GA_LD)
#define GB_SZ (16 * GB_LD)
#define GSTAGE (2 * GA_SZ + 2 * GB_SZ)
#define GEMM_SMEM (2 * GSTAGE * 4)

template <bool TERM3>
__device__ __forceinline__ void gemm_issue(uint32_t sbase, const uint32_t* __restrict__ Ah,
                                           const uint32_t* __restrict__ Al,
                                           const uint32_t* __restrict__ Bh,
                                           const uint32_t* __restrict__ Bl,
                                           int brow, int bcol, int kt2, int K2, int Nc, int tid) {
    int ra = tid >> 2, ca = (tid & 3) << 2;
    int rb = tid >> 5, cb = (tid & 31) << 2;
#pragma unroll
    for (int p = 0; p < 2; p++) {
        int r = p * 64 + ra;
        size_t ga = (size_t)(brow + r) * K2 + kt2 + ca;
        uint32_t da = sbase + (r * GA_LD + ca) * 4;
        cp16(da, Ah + ga);
        if (TERM3) cp16(da + GA_SZ * 4, Al + ga);
        int r2 = p * 8 + rb;
        size_t gb = (size_t)(kt2 + r2) * Nc + bcol + cb;
        uint32_t db = sbase + (2 * GA_SZ + r2 * GB_LD + cb) * 4;
        cp16(db, Bh + gb);
        cp16(db + GB_SZ * 4, Bl + gb);
    }
}

template <bool TERM3>
__global__ __launch_bounds__(256, 2) void gemm_bf16(const uint32_t* __restrict__ Ah,
                                                    const uint32_t* __restrict__ Al,
                                                    const uint32_t* __restrict__ Bh,
                                                    const uint32_t* __restrict__ Bl,
                                                    float* __restrict__ C,
                                                    int M, int Nc, int K2) {
    extern __shared__ uint32_t smem_u[];
    int tid = threadIdx.x;
    int lane = tid & 31, warp = tid >> 5;
    int brow = blockIdx.y * 128, bcol = blockIdx.x * 128;
    int wm = (warp >> 1) * 32, wn = (warp & 1) * 64;
    int g = lane >> 2, tg = lane & 3;
    uint32_t sbase = (uint32_t)__cvta_generic_to_shared(smem_u);

    float acc[2][8][4];
#pragma unroll
    for (int mi = 0; mi < 2; mi++)
#pragma unroll
        for (int ni = 0; ni < 8; ni++)
#pragma unroll
            for (int e = 0; e < 4; e++) acc[mi][ni][e] = 0.f;

    gemm_issue<TERM3>(sbase, Ah, Al, Bh, Bl, brow, bcol, 0, K2, Nc, tid);
    asm volatile("cp.async.commit_group;");

    int KT = K2 >> 4;
    for (int t = 0; t < KT; t++) {
        if (t + 1 < KT) {
            gemm_issue<TERM3>(sbase + ((t + 1) & 1) * GSTAGE * 4, Ah, Al, Bh, Bl,
                              brow, bcol, (t + 1) << 4, K2, Nc, tid);
            asm volatile("cp.async.commit_group;");
            asm volatile("cp.async.wait_group 1;");
        } else {
            asm volatile("cp.async.wait_group 0;");
        }
        __syncthreads();
        const uint32_t* st = smem_u + (t & 1) * GSTAGE;
        const uint32_t* sAh = st;
        const uint32_t* sAl = st + GA_SZ;
        const uint32_t* sBh = st + 2 * GA_SZ;
        const uint32_t* sBl = st + 2 * GA_SZ + GB_SZ;
#pragma unroll
        for (int kh = 0; kh < 2; kh++) {
            int k8 = kh * 8;
            uint32_t ah[2][4], al[2][4];
#pragma unroll
            for (int mi = 0; mi < 2; mi++) {
                int r0 = (wm + mi * 16 + g) * GA_LD + k8 + tg;
                int r1 = r0 + 8 * GA_LD;
                ah[mi][0] = sAh[r0];     ah[mi][1] = sAh[r1];
                ah[mi][2] = sAh[r0 + 4]; ah[mi][3] = sAh[r1 + 4];
                if (TERM3) {
                    al[mi][0] = sAl[r0];     al[mi][1] = sAl[r1];
                    al[mi][2] = sAl[r0 + 4]; al[mi][3] = sAl[r1 + 4];
                }
            }
#pragma unroll
            for (int ni = 0; ni < 8; ni++) {
                int nb = (k8 + tg) * GB_LD + wn + ni * 8 + g;
                uint32_t bh0 = sBh[nb], bh1 = sBh[nb + 4 * GB_LD];
                uint32_t bl0 = sBl[nb], bl1 = sBl[nb + 4 * GB_LD];
#pragma unroll
                for (int mi = 0; mi < 2; mi++) {
                    mma_bf16(acc[mi][ni], ah[mi], bh0, bh1);
                    mma_bf16(acc[mi][ni], ah[mi], bl0, bl1);
                    if (TERM3) mma_bf16(acc[mi][ni], al[mi], bh0, bh1);
                }
            }
        }
        __syncthreads();
    }

#pragma unroll
    for (int mi = 0; mi < 2; mi++)
#pragma unroll
        for (int ni = 0; ni < 8; ni++) {
            int r = brow + wm + mi * 16 + g;
            int cx = bcol + wn + ni * 8 + tg * 2;
            float2 lo = {acc[mi][ni][0], acc[mi][ni][1]};
            float2 hi = {acc[mi][ni][2], acc[mi][ni][3]};
            *(float2*)(C + (size_t)r * Nc + cx) = lo;
            *(float2*)(C + (size_t)(r + 8) * Nc + cx) = hi;
        }
}

// ---------------- tensor-core 64x64x64 from smem tf32 hi/lo, selectable terms ----------------
#define CLD 68
#define BUF (64 * CLD)

template <bool TA, bool TB, bool AL, bool BL>
__device__ __forceinline__ void mm64_tc(const uint32_t* __restrict__ Ah,
                                        const uint32_t* __restrict__ Al,
                                        const uint32_t* __restrict__ Bh,
                                        const uint32_t* __restrict__ Bl,
                                        float acc[4][4], int m0, int n0, int g, int tg) {
#pragma unroll
    for (int ni = 0; ni < 4; ni++)
#pragma unroll
        for (int e = 0; e < 4; e++) acc[ni][e] = 0.f;
#pragma unroll 2
    for (int k8 = 0; k8 < 64; k8 += 8) {
        uint32_t ah[4], al[4] = {0, 0, 0, 0};
        if (!TA) {
            int ba = (m0 + g) * CLD + k8 + tg;
            ah[0] = Ah[ba]; ah[1] = Ah[ba + 8 * CLD]; ah[2] = Ah[ba + 4]; ah[3] = Ah[ba + 8 * CLD + 4];
            if (AL) {
                al[0] = Al[ba]; al[1] = Al[ba + 8 * CLD]; al[2] = Al[ba + 4]; al[3] = Al[ba + 8 * CLD + 4];
            }
        } else {
            int ba = (k8 + tg) * CLD + m0 + g;
            ah[0] = Ah[ba]; ah[1] = Ah[ba + 8]; ah[2] = Ah[ba + 4 * CLD]; ah[3] = Ah[ba + 4 * CLD + 8];
            if (AL) {
                al[0] = Al[ba]; al[1] = Al[ba + 8]; al[2] = Al[ba + 4 * CLD]; al[3] = Al[ba + 4 * CLD + 8];
            }
        }
#pragma unroll
        for (int ni = 0; ni < 4; ni++) {
            uint32_t bh0, bh1, bl0 = 0, bl1 = 0;
            if (!TB) {
                int bb = (k8 + tg) * CLD + n0 + ni * 8 + g;
                bh0 = Bh[bb]; bh1 = Bh[bb + 4 * CLD];
                if (BL) { bl0 = Bl[bb]; bl1 = Bl[bb + 4 * CLD]; }
            } else {
                int bb = (n0 + ni * 8 + g) * CLD + k8 + tg;
                bh0 = Bh[bb]; bh1 = Bh[bb + 4];
                if (BL) { bl0 = Bl[bb]; bl1 = Bl[bb + 4]; }
            }
            mma_tf32(acc[ni], ah, bh0, bh1);
            if (BL) mma_tf32(acc[ni], ah, bl0, bl1);
            if (AL) mma_tf32(acc[ni], al, bh0, bh1);
        }
    }
}

// fragment (row, col): e0=(g,2tg) e1=(g,2tg+1) e2=(g+8,2tg) e3=(g+8,2tg+1)
#define FRAG_ROW(e) (m0 + g + ((e) >> 1 ? 8 : 0))
#define FRAG_COL(ni, e) (n0 + (ni) * 8 + 2 * tg + ((e) & 1))

// ---------------- K4: per-chunk MLP gradients (6 smem bufs -> 2 CTAs/SM) ----------------
#define CG_SMEM (6 * BUF * 4)
__global__ __launch_bounds__(256, 2) void chunk_grad_tc(const float* __restrict__ w1,
                                                        const float* __restrict__ w2) {
    int id = blockIdx.x;               // bh*N_ + nn
    int bh = id >> 7, nn = id & 127;
    int b = bh >> 3, h = bh & 7;
    size_t tb = (size_t)b * T_ + (size_t)nn * C_;
    extern __shared__ uint32_t smu2[];
    uint32_t* KCh = smu2;
    uint32_t* HHh = smu2 + BUF;
    uint32_t* HHl = smu2 + 2 * BUF;
    uint32_t* W2h = smu2 + 3 * BUF;
    uint32_t* W2l = smu2 + 4 * BUF;
    uint32_t* G2h = smu2 + 5 * BUF;
    __shared__ float lrs[64];
    int tid = threadIdx.x;
    if (tid < 64) lrs[tid] = g_lr[(tb + tid) * H_ + h];
    for (int idx = tid; idx < 4096; idx += 256) {
        int i = idx >> 6, j = idx & 63;
        float kc = g_kv[(tb + i) * (2 * DIM_) + h * 64 + j];
        KCh[i * CLD + j] = f2tf(kc);
        float a1 = w1[idx];
        uint32_t hi = f2tf(a1);
        HHh[i * CLD + j] = hi; HHl[i * CLD + j] = f2tf(a1 - __uint_as_float(hi));
        float a2 = w2[idx];
        hi = f2tf(a2);
        W2h[i * CLD + j] = hi; W2l[i * CLD + j] = f2tf(a2 - __uint_as_float(hi));
    }
    __syncthreads();
    int lane = tid & 31, warp = tid >> 5;
    int m0 = (warp >> 1) * 16, n0 = (warp & 1) * 32;
    int g = lane >> 2, tg = lane & 3;
    float acc[4][4], x1s[4][4];

    // MM1: X1 = KC(hi) @ W1(hi/lo); X1 in regs; HH = silu(X1) hi/lo
    mm64_tc<false, false, false, true>(KCh, nullptr, HHh, HHl, acc, m0, n0, g, tg);
    __syncthreads();
#pragma unroll
    for (int ni = 0; ni < 4; ni++)
#pragma unroll
        for (int e = 0; e < 4; e++) {
            int row = FRAG_ROW(e), col = FRAG_COL(ni, e);
            float x = acc[ni][e];
            x1s[ni][e] = x;
            float hv = x * sigmoidf_(x);
            uint32_t hi = f2tf(hv);
            HHh[row * CLD + col] = hi;
            HHl[row * CLD + col] = f2tf(hv - __uint_as_float(hi));
        }
    __syncthreads();

    // MM2: X2 = HH @ W2 [3-term] ; G2 hi only
    mm64_tc<false, false, true, true>(HHh, HHl, W2h, W2l, acc, m0, n0, g, tg);
#pragma unroll
    for (int ni = 0; ni < 4; ni++)
#pragma unroll
        for (int e = 0; e < 4; e++) {
            int row = FRAG_ROW(e), col = FRAG_COL(ni, e);
            float vc = g_kv[(tb + row) * (2 * DIM_) + DIM_ + h * 64 + col];
            float gg = (2.f / 64.f) * lrs[row] * (acc[ni][e] - vc);
            G2h[row * CLD + col] = f2tf(gg);
        }
    __syncthreads();

    // MM3: g2 = HH^T @ G2(hi) -> -g2
    mm64_tc<true, false, true, false>(HHh, HHl, G2h, nullptr, acc, m0, n0, g, tg);
    size_t gbase = (size_t)id * 4096;
#pragma unroll
    for (int ni = 0; ni < 4; ni++) {
        int col = n0 + ni * 8 + 2 * tg;
        float2 v0 = {-acc[ni][0], -acc[ni][1]};
        float2 v1 = {-acc[ni][2], -acc[ni][3]};
        *(float2*)(g_g2 + gbase + (m0 + g) * 64 + col) = v0;
        *(float2*)(g_g2 + gbase + (m0 + 8 + g) * 64 + col) = v1;
    }
    __syncthreads();

    // MM4: DX1 = (G2(hi) @ W2^T) * silu'(X1) -> HH bufs
    mm64_tc<false, true, false, true>(G2h, nullptr, W2h, W2l, acc, m0, n0, g, tg);
#pragma unroll
    for (int ni = 0; ni < 4; ni++)
#pragma unroll
        for (int e = 0; e < 4; e++) {
            int row = FRAG_ROW(e), col = FRAG_COL(ni, e);
            float x = x1s[ni][e];
            float sg = sigmoidf_(x);
            float dv = acc[ni][e] * sg * (1.f + x * (1.f - sg));
            uint32_t hi = f2tf(dv);
            HHh[row * CLD + col] = hi;
            HHl[row * CLD + col] = f2tf(dv - __uint_as_float(hi));
        }
    __syncthreads();

    // MM5: g1 = KC^T(hi) @ DX1 -> -g1
    mm64_tc<true, false, false, true>(KCh, nullptr, HHh, HHl, acc, m0, n0, g, tg);
#pragma unroll
    for (int ni = 0; ni < 4; ni++) {
        int col = n0 + ni * 8 + 2 * tg;
        float2 v0 = {-acc[ni][0], -acc[ni][1]};
        float2 v1 = {-acc[ni][2], -acc[ni][3]};
        *(float2*)(g_g1 + gbase + (m0 + g) * 64 + col) = v0;
        *(float2*)(g_g1 + gbase + (m0 + 8 + g) * 64 + col) = v1;
    }
}

// ---------------- K5: double assoc-scan over n=128 chunks ----------------
__global__ __launch_bounds__(256) void scan_kernel(const float* __restrict__ w1,
                                                   const float* __restrict__ w2) {
    int bh = blockIdx.y;
    int idx = blockIdx.x * 256 + threadIdx.x;
    int b = bh >> 3, h = bh & 7;
    float w1v = w1[idx], w2v = w2[idx];
    float m1 = 0.f, u1 = 0.f, m2 = 0.f, u2 = 0.f;
    size_t base = ((size_t)bh * N_) * 4096 + idx;
    for (int nn = 0; nn < N_; nn++) {
        float mg = g_mom[((size_t)b * N_ + nn) * H_ + h];
        float dc = g_dec[((size_t)b * N_ + nn) * H_ + h];
        size_t off = base + (size_t)nn * 4096;
        float s1 = g_g1[off], s2 = g_g2[off];
        m1 = mg * m1 + s1; u1 = (1.f - dc) * u1 + m1; g_g1[off] = w1v + u1;
        m2 = mg * m2 + s2; u2 = (1.f - dc) * u2 + m2; g_g2[off] = w2v + u2;
    }
}

// ---------------- zero first 63 rows of packed vals per batch ----------------
__global__ void zero_pad_kernel() {
    int idx = blockIdx.x * 256 + threadIdx.x;
    const int per = 63 * DIM2_;
    if (idx < B_ * per) {
        int b = idx / per, r = idx % per;
        g_vhp[(size_t)b * T_ * DIM2_ + r] = 0u;
        g_vlp[(size_t)b * T_ * DIM2_ + r] = 0u;
    }
}

// ---------------- K6: retrieve — bf16 m16n8k16, packed layouts, 3-term ----------------
// A-ops [m][k2] LD 36; B-ops [k2][n] LD 72. All fills/epilogues are 32-bit stores.
#define RALD 36
#define RBLD 72
#define RBUF 2304              // max(64*36, 32*72) = 2304 u32
#define RT_SMEM (6 * RBUF * 4)

template <bool AL>
__device__ __forceinline__ void mm64_rbf(const uint32_t* __restrict__ Ah,
                                         const uint32_t* __restrict__ Al,
                                         const uint32_t* __restrict__ Bh,
                                         const uint32_t* __restrict__ Bl,
                                         float acc[4][4], int m0, int n0, int g, int tg) {
#pragma unroll
    for (int ni = 0; ni < 4; ni++)
#pragma unroll
        for (int e = 0; e < 4; e++) acc[ni][e] = 0.f;
#pragma unroll
    for (int k8 = 0; k8 < 32; k8 += 8) {     // k2 blocks (k16 each)
        uint32_t ah[4], al[4] = {0, 0, 0, 0};
        int ra = (m0 + g) * RALD + k8 + tg;
        int ra8 = ra + 8 * RALD;
        ah[0] = Ah[ra]; ah[1] = Ah[ra8]; ah[2] = Ah[ra + 4]; ah[3] = Ah[ra8 + 4];
        if (AL) {
            al[0] = Al[ra]; al[1] = Al[ra8]; al[2] = Al[ra + 4]; al[3] = Al[ra8 + 4];
        }
#pragma unroll
        for (int ni = 0; ni < 4; ni++) {
            int rb = (k8 + tg) * RBLD + n0 + ni * 8 + g;
            uint32_t bh0 = Bh[rb], bh1 = Bh[rb + 4 * RBLD];
            uint32_t bl0 = Bl[rb], bl1 = Bl[rb + 4 * RBLD];
            mma_bf16(acc[ni], ah, bh0, bh1);
            mma_bf16(acc[ni], ah, bl0, bl1);
            if (AL) mma_bf16(acc[ni], al, bh0, bh1);
        }
    }
}

__global__ __launch_bounds__(256, 2) void retrieve_bf(const float* __restrict__ gamma) {
    int id = blockIdx.x;
    int bh = id >> 7, nn = id & 127;
    int b = bh >> 3, h = bh & 7;
    extern __shared__ uint32_t smu3[];
    uint32_t* QAh = smu3;               // Q hi   [m][k2]
    uint32_t* QAl = smu3 + RBUF;        // Q lo
    uint32_t* W1h = smu3 + 2 * RBUF;    // W1eff hi [k2][n] -> HH hi [m][k2]
    uint32_t* W1l = smu3 + 3 * RBUF;    // W1eff lo -> HH lo
    uint32_t* W2h = smu3 + 4 * RBUF;    // W2eff hi [k2][n]
    uint32_t* W2l = smu3 + 5 * RBUF;    // W2eff lo
    __shared__ float rowp[64][2];
    __shared__ float gam[64];
    __shared__ float rscale[64];
    int tid = threadIdx.x;
    int j0 = nn * C_;
    size_t gbase = (size_t)id * 4096;
    if (tid < 64) gam[tid] = gamma[h * 64 + tid] + 1.f;

    for (int idx = tid; idx < 2048; idx += 256) {
        // Q: [ci][a2] from contiguous row
        int ci = idx >> 5, a2 = idx & 31;
        int i = j0 + ci + 63;
        float q0 = 0.f, q1 = 0.f;
        if (i < T_) {
            float2 qq = *(const float2*)(g_q + ((size_t)b * T_ + i) * DIM_ + h * 64 + 2 * a2);
            q0 = qq.x; q1 = qq.y;
        }
        QAh[ci * RALD + a2] = pack_bf2(q0, q1);
        QAl[ci * RALD + a2] = pack_bf2(q0 - bf16f(q0), q1 - bf16f(q1));
        // W1eff / W2eff: [k2][n], pack along k (row dim of g_g1)
        int k2 = idx >> 6, n = idx & 63;
        float e0 = g_g1[gbase + (size_t)(2 * k2) * 64 + n];
        float e1 = g_g1[gbase + (size_t)(2 * k2 + 1) * 64 + n];
        W1h[k2 * RBLD + n] = pack_bf2(e0, e1);
        W1l[k2 * RBLD + n] = pack_bf2(e0 - bf16f(e0), e1 - bf16f(e1));
        e0 = g_g2[gbase + (size_t)(2 * k2) * 64 + n];
        e1 = g_g2[gbase + (size_t)(2 * k2 + 1) * 64 + n];
        W2h[k2 * RBLD + n] = pack_bf2(e0, e1);
        W2l[k2 * RBLD + n] = pack_bf2(e0 - bf16f(e0), e1 - bf16f(e1));
    }
    __syncthreads();
    int lane = tid & 31, warp = tid >> 5;
    int m0 = (warp >> 1) * 16, n0 = (warp & 1) * 32;
    int g = lane >> 2, tg = lane & 3;
    float acc[4][4];

    // MM1: X1 = Q @ W1eff ; HH = silu(X1) -> overwrite W1 bufs in A-layout [m][k2]
    mm64_rbf<true>(QAh, QAl, W1h, W1l, acc, m0, n0, g, tg);
    __syncthreads();   // all warps done reading W1eff
#pragma unroll
    for (int ni = 0; ni < 4; ni++) {
        int c2 = (n0 + ni * 8) / 2 + tg;       // (col 2tg pair) -> word index
        float v0 = acc[ni][0], v1 = acc[ni][1];
        float h0 = v0 * sigmoidf_(v0), h1 = v1 * sigmoidf_(v1);
        int r0 = m0 + g;
        W1h[r0 * RALD + c2] = pack_bf2(h0, h1);
        W1l[r0 * RALD + c2] = pack_bf2(h0 - bf16f(h0), h1 - bf16f(h1));
        float v2 = acc[ni][2], v3 = acc[ni][3];
        float h2 = v2 * sigmoidf_(v2), h3 = v3 * sigmoidf_(v3);
        int r1 = m0 + 8 + g;
        W1h[r1 * RALD + c2] = pack_bf2(h2, h3);
        W1l[r1 * RALD + c2] = pack_bf2(h2 - bf16f(h2), h3 - bf16f(h3));
    }
    __syncthreads();

    // MM2: Y = HH @ W2eff (stays in acc)
    mm64_rbf<true>(W1h, W1l, W2h, W2l, acc, m0, n0, g, tg);

    // per-row sum of squares via shfl over tg lanes
    float ss0 = 0.f, ss1 = 0.f;
#pragma unroll
    for (int ni = 0; ni < 4; ni++) {
        ss0 += acc[ni][0] * acc[ni][0] + acc[ni][1] * acc[ni][1];
        ss1 += acc[ni][2] * acc[ni][2] + acc[ni][3] * acc[ni][3];
    }
#pragma unroll
    for (int o = 1; o < 4; o <<= 1) {
        ss0 += __shfl_xor_sync(0xffffffffu, ss0, o);
        ss1 += __shfl_xor_sync(0xffffffffu, ss1, o);
    }
    if (tg == 0) {
        rowp[m0 + g][warp & 1] = ss0;
        rowp[m0 + 8 + g][warp & 1] = ss1;
    }
    __syncthreads();
    if (tid < 64) {
        int i = j0 + tid + 63;
        float gate = (i < T_) ? g_gate[((size_t)b * T_ + i) * H_ + h] : 0.f;
        float tot = rowp[tid][0] + rowp[tid][1];
        rscale[tid] = rsqrtf(tot * (1.f / 64.f) + EPSV) * gate;
    }
    __syncthreads();

    // scale + gamma, emit packed bf16 hi/lo vals (adjacent column pairs)
#pragma unroll
    for (int ni = 0; ni < 4; ni++) {
        int col = n0 + ni * 8 + 2 * tg;
        float ga0 = gam[col], ga1 = gam[col + 1];
#pragma unroll
        for (int half = 0; half < 2; half++) {
            int row = m0 + g + half * 8;
            int i = j0 + row + 63;
            if (i < T_) {
                float rs = rscale[row];
                float v0 = acc[ni][half * 2 + 0] * rs * ga0;
                float v1 = acc[ni][half * 2 + 1] * rs * ga1;
                size_t oidx = ((size_t)b * T_ + i) * DIM2_ + ((h * 64 + col) >> 1);
                g_vhp[oidx] = pack_bf2(v0, v1);
                g_vlp[oidx] = pack_bf2(v0 - bf16f(v0), v1 - bf16f(v1));
            }
        }
    }
}

// ---------------- launch ----------------
extern "C" void kernel_launch(void* const* d_in, const int* in_sizes, int n_in,
                              void* d_out, int out_size) {
    const float* seq      = (const float*)d_in[0];
    const float* w1       = (const float*)d_in[1];
    const float* w2       = (const float*)d_in[2];
    const float* Wq       = (const float*)d_in[3];
    const float* Wkv      = (const float*)d_in[4];
    const float* Wstep    = (const float*)d_in[5];
    const float* Wmom     = (const float*)d_in[6];
    const float* Wdecay   = (const float*)d_in[7];
    const float* Wgate    = (const float*)d_in[8];
    const float* Wcombine = (const float*)d_in[9];
    const float* gamma    = (const float*)d_in[10];
    float* out = (float*)d_out;
    (void)in_sizes; (void)n_in; (void)out_size;

    cudaFuncSetAttribute(gemm_bf16<true>, cudaFuncAttributeMaxDynamicSharedMemorySize, GEMM_SMEM);
    cudaFuncSetAttribute(gemm_bf16<false>, cudaFuncAttributeMaxDynamicSharedMemorySize, GEMM_SMEM);
    cudaFuncSetAttribute(chunk_grad_tc, cudaFuncAttributeMaxDynamicSharedMemorySize, CG_SMEM);
    cudaFuncSetAttribute(retrieve_bf, cudaFuncAttributeMaxDynamicSharedMemorySize, RT_SMEM);

    uint32_t *p_shp, *p_slp, *p_vhp, *p_vlp;
    uint32_t *p_wkvh, *p_wkvl, *p_wqh, *p_wql, *p_wch, *p_wcl;
    float *p_kv, *p_q;
    cudaGetSymbolAddress((void**)&p_shp, g_shp);
    cudaGetSymbolAddress((void**)&p_slp, g_slp);
    cudaGetSymbolAddress((void**)&p_vhp, g_vhp);
    cudaGetSymbolAddress((void**)&p_vlp, g_vlp);
    cudaGetSymbolAddress((void**)&p_wkvh, g_wkvh);
    cudaGetSymbolAddress((void**)&p_wkvl, g_wkvl);
    cudaGetSymbolAddress((void**)&p_wqh, g_wqh);
    cudaGetSymbolAddress((void**)&p_wql, g_wql);
    cudaGetSymbolAddress((void**)&p_wch, g_wch);
    cudaGetSymbolAddress((void**)&p_wcl, g_wcl);
    cudaGetSymbolAddress((void**)&p_kv, g_kv);
    cudaGetSymbolAddress((void**)&p_q, g_q);

    rmsnorm_kernel<<<B_ * T_, 256>>>(seq);
    cvtpack_kernel<<<(DIM2_ * 2 * DIM_ + 255) / 256, 256>>>(Wkv, p_wkvh, p_wkvl, DIM2_, 2 * DIM_);
    cvtpack_kernel<<<(DIM2_ * DIM_ + 255) / 256, 256>>>(Wq, p_wqh, p_wql, DIM2_, DIM_);
    cvtpack_kernel<<<(DIM2_ * DIM_ + 255) / 256, 256>>>(Wcombine, p_wch, p_wcl, DIM2_, DIM_);
    proj_kernel<<<B_ * N_, 256>>>(Wstep, Wgate, Wmom, Wdecay);
    // Wkv: 2-term (store path, error dampened through grads/scan)
    gemm_bf16<false><<<dim3(2 * DIM_ / 128, B_ * T_ / 128), 256, GEMM_SMEM>>>(
        p_shp, p_slp, p_wkvh, p_wkvl, p_kv, B_ * T_, 2 * DIM_, DIM2_);
    // Wq: 3-term (feeds retrieve directly)
    gemm_bf16<true><<<dim3(DIM_ / 128, B_ * T_ / 128), 256, GEMM_SMEM>>>(
        p_shp, p_slp, p_wqh, p_wql, p_q, B_ * T_, DIM_, DIM2_);
    chunk_grad_tc<<<BH_ * N_, 256, CG_SMEM>>>(w1, w2);
    scan_kernel<<<dim3(16, BH_), 256>>>(w1, w2);
    zero_pad_kernel<<<(B_ * 63 * DIM2_ + 255) / 256, 256>>>();
    retrieve_bf<<<BH_ * N_, 256, RT_SMEM>>>(gamma);
    // out: 3-term (output path)
    gemm_bf16<true><<<dim3(DIM_ / 128, B_ * T_ / 128), 256, GEMM_SMEM>>>(
        p_vhp, p_vlp, p_wch, p_wcl, out, B_ * T_, DIM_, DIM2_);
}